// round 2
// baseline (speedup 1.0000x reference)
#include <cuda_runtime.h>
#include <math.h>

#define S_LEN 1001
#define NBATCH 16
#define DIM 512
#define BAND 50
#define MROWS (NBATCH * S_LEN)            // 16016
#define SCORE_SCALE 0.044194173824159216f // 1/sqrt(512)

// Scratch for Q, K, V: 3 * 16016 * 512 floats (~98 MB)
__device__ float g_QKV[(size_t)3 * MROWS * DIM];

// ---------------------------------------------------------------------------
// Fused QKV projection: out = x @ W + b for W in {Wq, Wk, Wv}.
// Grid: (ceil(16016/128)=126, 12) — blockIdx.y selects (matrix, n-tile).
// 128x128 output tile, 256 threads, 8x8 per-thread microtile, K-step 16.
// ---------------------------------------------------------------------------
__global__ __launch_bounds__(256, 2) void qkv_gemm(
    const float* __restrict__ x,
    const float* __restrict__ Wq, const float* __restrict__ bq,
    const float* __restrict__ Wk, const float* __restrict__ bk,
    const float* __restrict__ Wv, const float* __restrict__ bv)
{
    __shared__ __align__(16) float As[16][128];
    __shared__ __align__(16) float Bs[16][128];

    const int tid = threadIdx.x;
    const int m0  = blockIdx.x * 128;
    const int nt  = blockIdx.y;
    const int which = nt >> 2;          // 0=Q, 1=K, 2=V
    const int n0    = (nt & 3) * 128;   // column tile within the 512-wide matrix

    const float* __restrict__ W    = (which == 0) ? Wq : (which == 1) ? Wk : Wv;
    const float* __restrict__ bias = (which == 0) ? bq : (which == 1) ? bk : bv;
    float* outp = g_QKV + (size_t)which * MROWS * DIM;

    const int tx = tid & 15;   // 0..15 -> col groups
    const int ty = tid >> 4;   // 0..15 -> row groups

    float c[8][8];
#pragma unroll
    for (int i = 0; i < 8; i++)
#pragma unroll
        for (int j = 0; j < 8; j++) c[i][j] = 0.0f;

    for (int kk = 0; kk < 512; kk += 16) {
        // Load A tile (128 rows x 16 k) transposed into As[k][m], and B tile.
#pragma unroll
        for (int l = 0; l < 2; l++) {
            int fid = tid + l * 256;
            // A: fid -> (row = fid/4, k4 = (fid%4)*4)
            int ar = fid >> 2;
            int ak = (fid & 3) * 4;
            int grow = m0 + ar;
            float4 av = make_float4(0.f, 0.f, 0.f, 0.f);
            if (grow < MROWS)
                av = *(const float4*)(x + (size_t)grow * 512 + kk + ak);
            As[ak + 0][ar] = av.x;
            As[ak + 1][ar] = av.y;
            As[ak + 2][ar] = av.z;
            As[ak + 3][ar] = av.w;
            // B: fid -> (k = fid/32, n4 = (fid%32)*4)
            int bk_ = fid >> 5;
            int bn  = (fid & 31) * 4;
            float4 bv4 = *(const float4*)(W + (size_t)(kk + bk_) * 512 + n0 + bn);
            *(float4*)&Bs[bk_][bn] = bv4;
        }
        __syncthreads();

#pragma unroll
        for (int k = 0; k < 16; k++) {
            float4 a0 = *(float4*)&As[k][ty * 4];
            float4 a1 = *(float4*)&As[k][64 + ty * 4];
            float4 b0 = *(float4*)&Bs[k][tx * 4];
            float4 b1 = *(float4*)&Bs[k][64 + tx * 4];
            float a[8] = {a0.x, a0.y, a0.z, a0.w, a1.x, a1.y, a1.z, a1.w};
            float bb[8] = {b0.x, b0.y, b0.z, b0.w, b1.x, b1.y, b1.z, b1.w};
#pragma unroll
            for (int i = 0; i < 8; i++)
#pragma unroll
                for (int j = 0; j < 8; j++) c[i][j] += a[i] * bb[j];
        }
        __syncthreads();
    }

    // Epilogue: bias + store.
    float bb0[4], bb1[4];
#pragma unroll
    for (int j = 0; j < 4; j++) {
        bb0[j] = bias[n0 + tx * 4 + j];
        bb1[j] = bias[n0 + 64 + tx * 4 + j];
    }
#pragma unroll
    for (int i = 0; i < 8; i++) {
        int lr = (i < 4) ? (ty * 4 + i) : (64 + ty * 4 + (i - 4));
        int gr = m0 + lr;
        if (gr >= MROWS) continue;
        float* orow = outp + (size_t)gr * 512 + n0;
        float4 v0, v1;
        v0.x = c[i][0] + bb0[0]; v0.y = c[i][1] + bb0[1];
        v0.z = c[i][2] + bb0[2]; v0.w = c[i][3] + bb0[3];
        v1.x = c[i][4] + bb1[0]; v1.y = c[i][5] + bb1[1];
        v1.z = c[i][6] + bb1[2]; v1.w = c[i][7] + bb1[3];
        *(float4*)(orow + tx * 4) = v0;
        *(float4*)(orow + 64 + tx * 4) = v1;
    }
}

// ---------------------------------------------------------------------------
// Band attention. Grid: (ceil(S/8)=126, B=16); block 256 (8 warps).
// Warp w owns row s = s0 + w. Softmax denominator & global max cancel against
// the post-softmax L2 renorm, so only band scores are computed:
//   attn_final[s,t] = exp(sc[t]-m_band) / sqrt(sum_band exp(sc-m_band)^2)
// K/V rows are staged through smem two at a time (one float4 per thread).
// ---------------------------------------------------------------------------
__global__ __launch_bounds__(256) void band_attn(float* __restrict__ outC,
                                                 float* __restrict__ outA)
{
    __shared__ __align__(16) float kv[1024];  // two staged K/V rows
    __shared__ float wsc[8][112];             // scores -> normalized weights

    const int tid  = threadIdx.x;
    const int lane = tid & 31;
    const int w    = tid >> 5;
    const int b    = blockIdx.y;
    const int s0   = blockIdx.x * 8;
    const int s    = s0 + w;
    const bool valid = (s < S_LEN);

    const int tlo  = max(0, s0 - BAND);
    const int thi  = min(S_LEN - 1, s0 + 7 + BAND);
    const int tcnt = thi - tlo + 1;           // <= 108

    const float* Q = g_QKV + (size_t)(b * S_LEN) * DIM;
    const float* K = g_QKV + ((size_t)MROWS + b * S_LEN) * DIM;
    const float* V = g_QKV + ((size_t)2 * MROWS + b * S_LEN) * DIM;

    // Q row in registers (lane-strided, coalesced)
    float q[16];
#pragma unroll
    for (int i = 0; i < 16; i++)
        q[i] = valid ? Q[(size_t)s * DIM + i * 32 + lane] : 0.0f;

    // ---- Phase A: band scores (2 K rows per barrier) --------------------
    for (int tt = 0; tt < tcnt; tt += 2) {
        __syncthreads();
        const int t0 = tlo + tt;
        const int nload = min(2, tcnt - tt);
        if (nload == 2)
            ((float4*)kv)[tid] = ((const float4*)(K + (size_t)t0 * DIM))[tid];
        else
            ((float2*)kv)[tid] = ((const float2*)(K + (size_t)t0 * DIM))[tid];
        __syncthreads();
#pragma unroll
        for (int u = 0; u < 2; u++) {
            if (u >= nload) break;
            float d = 0.0f;
#pragma unroll
            for (int i = 0; i < 16; i++) d += q[i] * kv[u * 512 + i * 32 + lane];
#pragma unroll
            for (int o = 16; o > 0; o >>= 1) d += __shfl_xor_sync(0xffffffffu, d, o);
            if (lane == 0) wsc[w][tt + u] = d * SCORE_SCALE;
        }
    }
    __syncthreads();

    // ---- Phase B: per-row exp + L2 renorm -------------------------------
    const int lo = valid ? (max(0, s - BAND) - tlo) : 0;
    const int hi = valid ? (min(S_LEN - 1, s + BAND) - tlo) : -1;

    float m = -3.0e38f;
    for (int j = lane; j < tcnt; j += 32)
        if (j >= lo && j <= hi) m = fmaxf(m, wsc[w][j]);
#pragma unroll
    for (int o = 16; o > 0; o >>= 1) m = fmaxf(m, __shfl_xor_sync(0xffffffffu, m, o));

    float sq = 0.0f;
    for (int j = lane; j < tcnt; j += 32) {
        float e = 0.0f;
        if (j >= lo && j <= hi) {
            e = expf(wsc[w][j] - m);
            sq += e * e;
        }
        wsc[w][j] = e;
    }
#pragma unroll
    for (int o = 16; o > 0; o >>= 1) sq += __shfl_xor_sync(0xffffffffu, sq, o);

    const float inv = (valid && sq > 0.0f) ? (1.0f / sqrtf(sq)) : 0.0f;
    for (int j = lane; j < tcnt; j += 32) wsc[w][j] *= inv;
    __syncwarp();

    if (valid && outA) {
        float* arow = outA + (size_t)(b * S_LEN + s) * S_LEN + tlo;
        for (int j = lo + lane; j <= hi; j += 32) arow[j] = wsc[w][j];
    }

    // ---- Phase C: compound = attn_final @ V (2 V rows per barrier) ------
    float acc[16];
#pragma unroll
    for (int i = 0; i < 16; i++) acc[i] = 0.0f;

    for (int tt = 0; tt < tcnt; tt += 2) {
        __syncthreads();
        const int t0 = tlo + tt;
        const int nload = min(2, tcnt - tt);
        if (nload == 2)
            ((float4*)kv)[tid] = ((const float4*)(V + (size_t)t0 * DIM))[tid];
        else
            ((float2*)kv)[tid] = ((const float2*)(V + (size_t)t0 * DIM))[tid];
        __syncthreads();
#pragma unroll
        for (int u = 0; u < 2; u++) {
            if (u >= nload) break;
            const float wt = wsc[w][tt + u];   // 0 outside band(s)
#pragma unroll
            for (int i = 0; i < 16; i++) acc[i] += wt * kv[u * 512 + i * 32 + lane];
        }
    }

    if (valid && outC) {
        float* crow = outC + (size_t)(b * S_LEN + s) * DIM;
#pragma unroll
        for (int i = 0; i < 16; i++) crow[i * 32 + lane] = acc[i];
    }
}

// ---------------------------------------------------------------------------
extern "C" void kernel_launch(void* const* d_in, const int* in_sizes, int n_in,
                              void* d_out, int out_size)
{
    const float* x  = (const float*)d_in[0];
    const float* Wq = (const float*)d_in[1];
    const float* bq = (const float*)d_in[2];
    const float* Wk = (const float*)d_in[3];
    const float* bk = (const float*)d_in[4];
    const float* Wv = (const float*)d_in[5];
    const float* bv = (const float*)d_in[6];
    // d_in[7] = local_mat: band is known analytically (|i-j| <= 50), unused.

    float* out = (float*)d_out;
    const long long NC = (long long)MROWS * DIM;    // compound_feature elems
    const long long NA = (long long)MROWS * S_LEN;  // attn_final elems

    float* comp = nullptr;
    float* attn = nullptr;
    if ((long long)out_size >= NC + NA) { comp = out; attn = out + NC; }
    else if ((long long)out_size == NA) { attn = out; }
    else                                { comp = out; }

    if (attn) cudaMemsetAsync(attn, 0, (size_t)NA * sizeof(float), 0);

    dim3 g1(126, 12);
    qkv_gemm<<<g1, 256>>>(x, Wq, bq, Wk, bk, Wv, bv);

    dim3 g2(126, NBATCH);
    band_attn<<<g2, 256>>>(comp, attn);
}

// round 4
// speedup vs baseline: 1.1383x; 1.1383x over previous
#include <cuda_runtime.h>
#include <math.h>

#define S_LEN 1001
#define NBATCH 16
#define DIM 512
#define BAND 50
#define MROWS (NBATCH * S_LEN)            // 16016
#define SCORE_SCALE 0.044194173824159216f // 1/sqrt(512)
#define STILE 32                          // s-rows per band_attn block
#define TCMAX 136                         // padded max band cols (132 actual)

// Scratch for Q, K, V: 3 * 16016 * 512 floats (~98 MB)
__device__ float g_QKV[(size_t)3 * MROWS * DIM];

// ---------------------------------------------------------------------------
// Fused QKV projection: out = x @ W + b for W in {Wq, Wk, Wv}.
// Grid: (126, 12). 128x128 tile, 256 threads, 8x8 microtile, K-step 16,
// double-buffered smem (one barrier per k-tile).
// ---------------------------------------------------------------------------
__global__ __launch_bounds__(256, 2) void qkv_gemm(
    const float* __restrict__ x,
    const float* __restrict__ Wq, const float* __restrict__ bq,
    const float* __restrict__ Wk, const float* __restrict__ bk,
    const float* __restrict__ Wv, const float* __restrict__ bv)
{
    __shared__ __align__(16) float As[2][16][128];
    __shared__ __align__(16) float Bs[2][16][128];

    const int tid = threadIdx.x;
    const int m0  = blockIdx.x * 128;
    const int nt  = blockIdx.y;
    const int which = nt >> 2;          // 0=Q, 1=K, 2=V
    const int n0    = (nt & 3) * 128;

    const float* __restrict__ W    = (which == 0) ? Wq : (which == 1) ? Wk : Wv;
    const float* __restrict__ bias = (which == 0) ? bq : (which == 1) ? bk : bv;
    float* outp = g_QKV + (size_t)which * MROWS * DIM;

    const int tx = tid & 15;
    const int ty = tid >> 4;

    // per-thread load coordinates (2 A-float4, 2 B-float4 per tile)
    const int ar0 = tid >> 2, ak0 = (tid & 3) * 4;          // A part 0
    const int ar1 = (tid + 256) >> 2, ak1 = ak0;            // A part 1
    const int bk0 = tid >> 5, bn0 = (tid & 31) * 4;         // B part 0
    const int bk1 = (tid + 256) >> 5, bn1 = bn0;            // B part 1

    float c[8][8];
#pragma unroll
    for (int i = 0; i < 8; i++)
#pragma unroll
        for (int j = 0; j < 8; j++) c[i][j] = 0.0f;

    // ---- prologue: load tile 0 into buffer 0
    {
        float4 a0 = make_float4(0.f,0.f,0.f,0.f), a1 = a0;
        if (m0 + ar0 < MROWS) a0 = *(const float4*)(x + (size_t)(m0 + ar0) * 512 + ak0);
        if (m0 + ar1 < MROWS) a1 = *(const float4*)(x + (size_t)(m0 + ar1) * 512 + ak1);
        float4 b0 = *(const float4*)(W + (size_t)bk0 * 512 + n0 + bn0);
        float4 b1 = *(const float4*)(W + (size_t)bk1 * 512 + n0 + bn1);
        As[0][ak0+0][ar0]=a0.x; As[0][ak0+1][ar0]=a0.y; As[0][ak0+2][ar0]=a0.z; As[0][ak0+3][ar0]=a0.w;
        As[0][ak1+0][ar1]=a1.x; As[0][ak1+1][ar1]=a1.y; As[0][ak1+2][ar1]=a1.z; As[0][ak1+3][ar1]=a1.w;
        *(float4*)&Bs[0][bk0][bn0] = b0;
        *(float4*)&Bs[0][bk1][bn1] = b1;
    }
    __syncthreads();

    for (int kk = 0; kk < 512; kk += 16) {
        const int cur = (kk >> 4) & 1;
        const int nxt = cur ^ 1;
        const bool more = (kk + 16 < 512);

        float4 pa0, pa1, pb0, pb1;
        if (more) {
            pa0 = make_float4(0.f,0.f,0.f,0.f); pa1 = pa0;
            if (m0 + ar0 < MROWS) pa0 = *(const float4*)(x + (size_t)(m0 + ar0) * 512 + kk + 16 + ak0);
            if (m0 + ar1 < MROWS) pa1 = *(const float4*)(x + (size_t)(m0 + ar1) * 512 + kk + 16 + ak1);
            pb0 = *(const float4*)(W + (size_t)(kk + 16 + bk0) * 512 + n0 + bn0);
            pb1 = *(const float4*)(W + (size_t)(kk + 16 + bk1) * 512 + n0 + bn1);
        }

#pragma unroll
        for (int k = 0; k < 16; k++) {
            float4 a0 = *(float4*)&As[cur][k][ty * 4];
            float4 a1 = *(float4*)&As[cur][k][64 + ty * 4];
            float4 b0 = *(float4*)&Bs[cur][k][tx * 4];
            float4 b1 = *(float4*)&Bs[cur][k][64 + tx * 4];
            float a[8]  = {a0.x, a0.y, a0.z, a0.w, a1.x, a1.y, a1.z, a1.w};
            float bb[8] = {b0.x, b0.y, b0.z, b0.w, b1.x, b1.y, b1.z, b1.w};
#pragma unroll
            for (int i = 0; i < 8; i++)
#pragma unroll
                for (int j = 0; j < 8; j++) c[i][j] += a[i] * bb[j];
        }

        if (more) {
            As[nxt][ak0+0][ar0]=pa0.x; As[nxt][ak0+1][ar0]=pa0.y; As[nxt][ak0+2][ar0]=pa0.z; As[nxt][ak0+3][ar0]=pa0.w;
            As[nxt][ak1+0][ar1]=pa1.x; As[nxt][ak1+1][ar1]=pa1.y; As[nxt][ak1+2][ar1]=pa1.z; As[nxt][ak1+3][ar1]=pa1.w;
            *(float4*)&Bs[nxt][bk0][bn0] = pb0;
            *(float4*)&Bs[nxt][bk1][bn1] = pb1;
        }
        __syncthreads();
    }

    // Epilogue: bias + store.
    float bb0[4], bb1[4];
#pragma unroll
    for (int j = 0; j < 4; j++) {
        bb0[j] = bias[n0 + tx * 4 + j];
        bb1[j] = bias[n0 + 64 + tx * 4 + j];
    }
#pragma unroll
    for (int i = 0; i < 8; i++) {
        int lr = (i < 4) ? (ty * 4 + i) : (64 + ty * 4 + (i - 4));
        int gr = m0 + lr;
        if (gr >= MROWS) continue;
        float* orow = outp + (size_t)gr * 512 + n0;
        float4 v0, v1;
        v0.x = c[i][0] + bb0[0]; v0.y = c[i][1] + bb0[1];
        v0.z = c[i][2] + bb0[2]; v0.w = c[i][3] + bb0[3];
        v1.x = c[i][4] + bb1[0]; v1.y = c[i][5] + bb1[1];
        v1.z = c[i][6] + bb1[2]; v1.w = c[i][7] + bb1[3];
        *(float4*)(orow + tx * 4) = v0;
        *(float4*)(orow + 64 + tx * 4) = v1;
    }
}

// ---------------------------------------------------------------------------
// Band attention, GEMM-formulated. Grid: (32, 16); block 256 (8 warps).
// Block owns 32 query rows. Softmax denom & global max cancel against the
// post-softmax L2 renorm -> only band scores needed:
//   attn_final[s,t] = exp(sc[t]-m_band) / sqrt(sum_band exp(sc-m_band)^2)
// Phase A: S[32 x tcnt] = Q Kt^T  (4x5 microtile, no shuffles)
// Phase C: C[32 x 512]  = A V     (4x16 microtile, 4 V rows per barrier)
// ---------------------------------------------------------------------------
__global__ __launch_bounds__(256) void band_attn(float* __restrict__ outC,
                                                 float* __restrict__ outA)
{
    __shared__ __align__(16) float Qs[STILE][16];
    __shared__ float Kt[TCMAX][17];          // stride 17: conflict-free col reads
    __shared__ float wsc[STILE][TCMAX];
    __shared__ __align__(16) float vstage[2048];   // 4 V rows

    const int tid = threadIdx.x;
    const int tx  = tid & 31;      // lane
    const int ty  = tid >> 5;      // warp
    const int b   = blockIdx.y;
    const int s0  = blockIdx.x * STILE;

    const int tlo  = max(0, s0 - BAND);
    const int thi  = min(S_LEN - 1, s0 + STILE - 1 + BAND);
    const int tcnt = thi - tlo + 1;                // <= 132

    const float* Q = g_QKV + (size_t)(b * S_LEN) * DIM;
    const float* K = g_QKV + ((size_t)MROWS + b * S_LEN) * DIM;
    const float* V = g_QKV + ((size_t)2 * MROWS + b * S_LEN) * DIM;

    // ---- Phase A: scores GEMM ------------------------------------------
    {
        float acc[4][5];
#pragma unroll
        for (int u = 0; u < 4; u++)
#pragma unroll
            for (int j = 0; j < 5; j++) acc[u][j] = 0.0f;

        const int qr = tid >> 3, qk = (tid & 7) * 2;   // Qs loader coords
        for (int kk = 0; kk < 512; kk += 16) {
            // Q tile: 32 rows x 16 k (reads past S_LEN stay inside g_QKV)
            *(float2*)&Qs[qr][qk] =
                *(const float2*)(Q + (size_t)(s0 + qr) * 512 + kk + qk);
            // K tile: tcnt rows x 16 k. Global load is float2; smem store must
            // be scalar: Kt stride 17 makes odd rows only 4B-aligned.
#pragma unroll
            for (int l = 0; l < 5; l++) {
                int idx = tid + l * 256;
                int row = idx >> 3, kq = (idx & 7) * 2;
                if (row < tcnt) {
                    float2 v = *(const float2*)(K + (size_t)(tlo + row) * 512 + kk + kq);
                    Kt[row][kq]     = v.x;
                    Kt[row][kq + 1] = v.y;
                }
            }
            __syncthreads();
#pragma unroll
            for (int k = 0; k < 16; k++) {
                float a[4], bb[5];
#pragma unroll
                for (int u = 0; u < 4; u++) a[u] = Qs[ty + 8 * u][k];
#pragma unroll
                for (int j = 0; j < 5; j++) bb[j] = Kt[tx + 32 * j][k];
#pragma unroll
                for (int u = 0; u < 4; u++)
#pragma unroll
                    for (int j = 0; j < 5; j++) acc[u][j] += a[u] * bb[j];
            }
            __syncthreads();
        }
#pragma unroll
        for (int u = 0; u < 4; u++)
#pragma unroll
            for (int j = 0; j < 5; j++) {
                int col = tx + 32 * j;
                if (col < tcnt) wsc[ty + 8 * u][col] = acc[u][j] * SCORE_SCALE;
            }
    }
    __syncthreads();

    // ---- Phase B: per-row exp + L2 renorm (warp per row) ----------------
#pragma unroll
    for (int u = 0; u < 4; u++) {
        const int row = ty + 8 * u;
        const int s   = s0 + row;
        const bool valid = (s < S_LEN);
        const int lo = valid ? (max(0, s - BAND) - tlo) : 0;
        const int hi = valid ? (min(S_LEN - 1, s + BAND) - tlo) : -1;

        float m = -3.0e38f;
        for (int j = tx; j < tcnt; j += 32)
            if (j >= lo && j <= hi) m = fmaxf(m, wsc[row][j]);
#pragma unroll
        for (int o = 16; o > 0; o >>= 1) m = fmaxf(m, __shfl_xor_sync(0xffffffffu, m, o));

        float sq = 0.0f;
        for (int j = tx; j < tcnt; j += 32) {
            float e = 0.0f;
            if (j >= lo && j <= hi) {
                e = expf(wsc[row][j] - m);
                sq += e * e;
            }
            wsc[row][j] = e;
        }
#pragma unroll
        for (int o = 16; o > 0; o >>= 1) sq += __shfl_xor_sync(0xffffffffu, sq, o);

        const float inv = (valid && sq > 0.0f) ? (1.0f / sqrtf(sq)) : 0.0f;
        for (int j = tx; j < tcnt; j += 32) wsc[row][j] *= inv;
        __syncwarp();

        if (valid && outA) {
            float* arow = outA + (size_t)(b * S_LEN + s) * S_LEN + tlo;
            for (int j = lo + tx; j <= hi; j += 32) arow[j] = wsc[row][j];
        }
    }
    __syncthreads();

    // ---- Phase C: compound GEMM (4 V rows per barrier) ------------------
    {
        float cacc[4][16];
#pragma unroll
        for (int u = 0; u < 4; u++)
#pragma unroll
            for (int j = 0; j < 16; j++) cacc[u][j] = 0.0f;

        for (int tt = 0; tt < tcnt; tt += 4) {
            const int nload = min(4, tcnt - tt);
            // stage nload V rows (each row = 512 floats; 256 thr -> float4/row/2thr)
#pragma unroll
            for (int l = 0; l < 2; l++) {
                int idx = tid + l * 256;           // 0..511 -> float4 slot
                int row = idx >> 7;                // 128 float4 per row
                if (row < nload)
                    ((float4*)vstage)[idx] =
                        ((const float4*)(V + (size_t)(tlo + tt + row) * 512))[idx & 127];
            }
            __syncthreads();
#pragma unroll
            for (int u2 = 0; u2 < 4; u2++) {
                if (u2 >= nload) break;
                float wt[4];
#pragma unroll
                for (int u = 0; u < 4; u++) wt[u] = wsc[ty + 8 * u][tt + u2];
#pragma unroll
                for (int j = 0; j < 16; j++) {
                    float v = vstage[u2 * 512 + tx + 32 * j];
#pragma unroll
                    for (int u = 0; u < 4; u++) cacc[u][j] += wt[u] * v;
                }
            }
            __syncthreads();
        }

        if (outC) {
#pragma unroll
            for (int u = 0; u < 4; u++) {
                const int s = s0 + ty + 8 * u;
                if (s >= S_LEN) continue;
                float* crow = outC + (size_t)(b * S_LEN + s) * DIM;
#pragma unroll
                for (int j = 0; j < 16; j++) crow[tx + 32 * j] = cacc[u][j];
            }
        }
    }
}

// ---------------------------------------------------------------------------
extern "C" void kernel_launch(void* const* d_in, const int* in_sizes, int n_in,
                              void* d_out, int out_size)
{
    const float* x  = (const float*)d_in[0];
    const float* Wq = (const float*)d_in[1];
    const float* bq = (const float*)d_in[2];
    const float* Wk = (const float*)d_in[3];
    const float* bk = (const float*)d_in[4];
    const float* Wv = (const float*)d_in[5];
    const float* bv = (const float*)d_in[6];
    // d_in[7] = local_mat: band known analytically (|i-j| <= 50), unused.

    float* out = (float*)d_out;
    const long long NC = (long long)MROWS * DIM;    // compound_feature elems
    const long long NA = (long long)MROWS * S_LEN;  // attn_final elems

    float* comp = nullptr;
    float* attn = nullptr;
    if ((long long)out_size >= NC + NA) { comp = out; attn = out + NC; }
    else if ((long long)out_size == NA) { attn = out; }
    else                                { comp = out; }

    if (attn) cudaMemsetAsync(attn, 0, (size_t)NA * sizeof(float), 0);

    dim3 g1(126, 12);
    qkv_gemm<<<g1, 256>>>(x, Wq, bq, Wk, bk, Wv, bv);

    dim3 g2((S_LEN + STILE - 1) / STILE, NBATCH);
    band_attn<<<g2, 256>>>(comp, attn);
}

// round 6
// speedup vs baseline: 1.2295x; 1.0802x over previous
#include <cuda_runtime.h>
#include <math.h>

#define S_LEN 1001
#define NBATCH 16
#define DIM 512
#define BAND 50
#define MROWS (NBATCH * S_LEN)            // 16016
#define SCORE_SCALE 0.044194173824159216f // 1/sqrt(512)
#define STILE 32
#define TCMAX 136

// Scratch: slice 0 = G = x @ (Wq Wk^T), slice 2 = V. (slice 1 unused)
__device__ float g_QKV[(size_t)3 * MROWS * DIM];
__device__ float g_M[512 * 512];          // Wq @ Wk^T
__device__ float g_w[512];                // Wk @ bq

// ---------------------------------------------------------------------------
// prep_w: g_w[i] = sum_d Wk[i,d] * bq[d]
// ---------------------------------------------------------------------------
__global__ void prep_w(const float* __restrict__ Wk, const float* __restrict__ bq)
{
    const int i = blockIdx.x * 256 + threadIdx.x;
    if (i < 512) {
        float s = 0.0f;
        const float* row = Wk + (size_t)i * 512;
#pragma unroll 8
        for (int d = 0; d < 512; d++) s += row[d] * bq[d];
        g_w[i] = s;
    }
}

// ---------------------------------------------------------------------------
// wqwk_gemm: M = Wq @ Wk^T  (both row-major, dot over their rows).
// Grid (4,4), 128x128 tile, 256 threads, 8x8 microtile.
// ---------------------------------------------------------------------------
__global__ __launch_bounds__(256) void wqwk_gemm(const float* __restrict__ Wq,
                                                 const float* __restrict__ Wk)
{
    __shared__ __align__(16) float As[16][128];
    __shared__ __align__(16) float Bs[16][128];

    const int tid = threadIdx.x;
    const int m0  = blockIdx.x * 128;
    const int n0  = blockIdx.y * 128;
    const int tx = tid & 15, ty = tid >> 4;

    float c[8][8];
#pragma unroll
    for (int i = 0; i < 8; i++)
#pragma unroll
        for (int j = 0; j < 8; j++) c[i][j] = 0.0f;

    for (int kk = 0; kk < 512; kk += 16) {
#pragma unroll
        for (int l = 0; l < 2; l++) {
            int fid = tid + l * 256;
            int r = fid >> 2, k4 = (fid & 3) * 4;
            float4 av = *(const float4*)(Wq + (size_t)(m0 + r) * 512 + kk + k4);
            As[k4+0][r] = av.x; As[k4+1][r] = av.y; As[k4+2][r] = av.z; As[k4+3][r] = av.w;
            float4 bv = *(const float4*)(Wk + (size_t)(n0 + r) * 512 + kk + k4);
            Bs[k4+0][r] = bv.x; Bs[k4+1][r] = bv.y; Bs[k4+2][r] = bv.z; Bs[k4+3][r] = bv.w;
        }
        __syncthreads();
#pragma unroll
        for (int k = 0; k < 16; k++) {
            float4 a0 = *(float4*)&As[k][ty * 4];
            float4 a1 = *(float4*)&As[k][64 + ty * 4];
            float4 b0 = *(float4*)&Bs[k][tx * 4];
            float4 b1 = *(float4*)&Bs[k][64 + tx * 4];
            float a[8]  = {a0.x, a0.y, a0.z, a0.w, a1.x, a1.y, a1.z, a1.w};
            float bb[8] = {b0.x, b0.y, b0.z, b0.w, b1.x, b1.y, b1.z, b1.w};
#pragma unroll
            for (int i = 0; i < 8; i++)
#pragma unroll
                for (int j = 0; j < 8; j++) c[i][j] += a[i] * bb[j];
        }
        __syncthreads();
    }
#pragma unroll
    for (int i = 0; i < 8; i++) {
        int lr = (i < 4) ? (ty * 4 + i) : (64 + ty * 4 + (i - 4));
        float* orow = g_M + (size_t)(m0 + lr) * 512 + n0;
        float4 v0 = {c[i][0], c[i][1], c[i][2], c[i][3]};
        float4 v1 = {c[i][4], c[i][5], c[i][6], c[i][7]};
        *(float4*)(orow + tx * 4) = v0;
        *(float4*)(orow + 64 + tx * 4) = v1;
    }
}

// ---------------------------------------------------------------------------
// qkv_gemm: out = x @ W (+ b). Grid (126, 8): y>>2 -> 0=G (W=g_M, no bias),
// 1=V (W=Wv, bias bv). 128x128 tile, double-buffered, 8x8 microtile.
// ---------------------------------------------------------------------------
__global__ __launch_bounds__(256, 2) void qkv_gemm(
    const float* __restrict__ x,
    const float* __restrict__ Wv, const float* __restrict__ bv)
{
    __shared__ __align__(16) float As[2][16][128];
    __shared__ __align__(16) float Bs[2][16][128];

    const int tid = threadIdx.x;
    const int m0  = blockIdx.x * 128;
    const int nt  = blockIdx.y;
    const int mat = nt >> 2;            // 0=G, 1=V
    const int n0  = (nt & 3) * 128;

    const float* __restrict__ W    = (mat == 0) ? g_M : Wv;
    const float* __restrict__ bias = (mat == 0) ? (const float*)0 : bv;
    float* outp = g_QKV + (size_t)(mat == 0 ? 0 : 2) * MROWS * DIM;

    const int tx = tid & 15;
    const int ty = tid >> 4;

    const int ar0 = tid >> 2, ak0 = (tid & 3) * 4;
    const int ar1 = (tid + 256) >> 2, ak1 = ak0;
    const int bk0 = tid >> 5, bn0 = (tid & 31) * 4;
    const int bk1 = (tid + 256) >> 5, bn1 = bn0;

    float c[8][8];
#pragma unroll
    for (int i = 0; i < 8; i++)
#pragma unroll
        for (int j = 0; j < 8; j++) c[i][j] = 0.0f;

    {
        float4 a0 = make_float4(0.f,0.f,0.f,0.f), a1 = a0;
        if (m0 + ar0 < MROWS) a0 = *(const float4*)(x + (size_t)(m0 + ar0) * 512 + ak0);
        if (m0 + ar1 < MROWS) a1 = *(const float4*)(x + (size_t)(m0 + ar1) * 512 + ak1);
        float4 b0 = *(const float4*)(W + (size_t)bk0 * 512 + n0 + bn0);
        float4 b1 = *(const float4*)(W + (size_t)bk1 * 512 + n0 + bn1);
        As[0][ak0+0][ar0]=a0.x; As[0][ak0+1][ar0]=a0.y; As[0][ak0+2][ar0]=a0.z; As[0][ak0+3][ar0]=a0.w;
        As[0][ak1+0][ar1]=a1.x; As[0][ak1+1][ar1]=a1.y; As[0][ak1+2][ar1]=a1.z; As[0][ak1+3][ar1]=a1.w;
        *(float4*)&Bs[0][bk0][bn0] = b0;
        *(float4*)&Bs[0][bk1][bn1] = b1;
    }
    __syncthreads();

    for (int kk = 0; kk < 512; kk += 16) {
        const int cur = (kk >> 4) & 1;
        const int nxt = cur ^ 1;
        const bool more = (kk + 16 < 512);

        float4 pa0, pa1, pb0, pb1;
        if (more) {
            pa0 = make_float4(0.f,0.f,0.f,0.f); pa1 = pa0;
            if (m0 + ar0 < MROWS) pa0 = *(const float4*)(x + (size_t)(m0 + ar0) * 512 + kk + 16 + ak0);
            if (m0 + ar1 < MROWS) pa1 = *(const float4*)(x + (size_t)(m0 + ar1) * 512 + kk + 16 + ak1);
            pb0 = *(const float4*)(W + (size_t)(kk + 16 + bk0) * 512 + n0 + bn0);
            pb1 = *(const float4*)(W + (size_t)(kk + 16 + bk1) * 512 + n0 + bn1);
        }

#pragma unroll
        for (int k = 0; k < 16; k++) {
            float4 a0 = *(float4*)&As[cur][k][ty * 4];
            float4 a1 = *(float4*)&As[cur][k][64 + ty * 4];
            float4 b0 = *(float4*)&Bs[cur][k][tx * 4];
            float4 b1 = *(float4*)&Bs[cur][k][64 + tx * 4];
            float a[8]  = {a0.x, a0.y, a0.z, a0.w, a1.x, a1.y, a1.z, a1.w};
            float bb[8] = {b0.x, b0.y, b0.z, b0.w, b1.x, b1.y, b1.z, b1.w};
#pragma unroll
            for (int i = 0; i < 8; i++)
#pragma unroll
                for (int j = 0; j < 8; j++) c[i][j] += a[i] * bb[j];
        }

        if (more) {
            As[nxt][ak0+0][ar0]=pa0.x; As[nxt][ak0+1][ar0]=pa0.y; As[nxt][ak0+2][ar0]=pa0.z; As[nxt][ak0+3][ar0]=pa0.w;
            As[nxt][ak1+0][ar1]=pa1.x; As[nxt][ak1+1][ar1]=pa1.y; As[nxt][ak1+2][ar1]=pa1.z; As[nxt][ak1+3][ar1]=pa1.w;
            *(float4*)&Bs[nxt][bk0][bn0] = pb0;
            *(float4*)&Bs[nxt][bk1][bn1] = pb1;
        }
        __syncthreads();
    }

    float bb0[4] = {0.f,0.f,0.f,0.f}, bb1[4] = {0.f,0.f,0.f,0.f};
    if (bias) {
#pragma unroll
        for (int j = 0; j < 4; j++) {
            bb0[j] = bias[n0 + tx * 4 + j];
            bb1[j] = bias[n0 + 64 + tx * 4 + j];
        }
    }
#pragma unroll
    for (int i = 0; i < 8; i++) {
        int lr = (i < 4) ? (ty * 4 + i) : (64 + ty * 4 + (i - 4));
        int gr = m0 + lr;
        if (gr >= MROWS) continue;
        float* orow = outp + (size_t)gr * 512 + n0;
        float4 v0, v1;
        v0.x = c[i][0] + bb0[0]; v0.y = c[i][1] + bb0[1];
        v0.z = c[i][2] + bb0[2]; v0.w = c[i][3] + bb0[3];
        v1.x = c[i][4] + bb1[0]; v1.y = c[i][5] + bb1[1];
        v1.z = c[i][6] + bb1[2]; v1.w = c[i][7] + bb1[3];
        *(float4*)(orow + tx * 4) = v0;
        *(float4*)(orow + 64 + tx * 4) = v1;
    }
}

// ---------------------------------------------------------------------------
// Band attention. scores'(s,t) = G_s . x_t + d_t  where d_t = x_t . g_w.
// Per-row-s constants cancel in exp/L2-renorm (as does softmax denom & max):
//   attn_final[s,t] = exp(sc-m)/sqrt(sum_band exp(sc-m)^2)
// ---------------------------------------------------------------------------
__global__ __launch_bounds__(256) void band_attn(float* __restrict__ outC,
                                                 float* __restrict__ outA,
                                                 const float* __restrict__ x)
{
    __shared__ __align__(16) float Qs[STILE][16];
    __shared__ float Kt[TCMAX][17];
    __shared__ float wsc[STILE][TCMAX];
    __shared__ float dsh[TCMAX];
    __shared__ __align__(16) float vstage[2048];

    const int tid = threadIdx.x;
    const int tx  = tid & 31;
    const int ty  = tid >> 5;
    const int b   = blockIdx.y;
    const int s0  = blockIdx.x * STILE;

    const int tlo  = max(0, s0 - BAND);
    const int thi  = min(S_LEN - 1, s0 + STILE - 1 + BAND);
    const int tcnt = thi - tlo + 1;

    const float* G  = g_QKV + (size_t)(b * S_LEN) * DIM;                 // "Q"
    const float* Kx = x + (size_t)(b * S_LEN) * DIM;                     // "K"
    const float* V  = g_QKV + ((size_t)2 * MROWS + b * S_LEN) * DIM;

    // ---- Phase A: scores GEMM + d_t -------------------------------------
    {
        float acc[4][5];
#pragma unroll
        for (int u = 0; u < 4; u++)
#pragma unroll
            for (int j = 0; j < 5; j++) acc[u][j] = 0.0f;
        float dloc = 0.0f;

        const int qr = tid >> 3, qk = (tid & 7) * 2;
        for (int kk = 0; kk < 512; kk += 16) {
            *(float2*)&Qs[qr][qk] =
                *(const float2*)(G + (size_t)(s0 + qr) * 512 + kk + qk);
#pragma unroll
            for (int l = 0; l < 5; l++) {
                int idx = tid + l * 256;
                int row = idx >> 3, kq = (idx & 7) * 2;
                if (row < tcnt) {
                    float2 v = *(const float2*)(Kx + (size_t)(tlo + row) * 512 + kk + kq);
                    Kt[row][kq]     = v.x;
                    Kt[row][kq + 1] = v.y;
                }
            }
            __syncthreads();

            if (tid < tcnt) {
#pragma unroll
                for (int k = 0; k < 16; k++) dloc += Kt[tid][k] * g_w[kk + k];
            }
#pragma unroll
            for (int k = 0; k < 16; k++) {
                float a[4], bb[5];
#pragma unroll
                for (int u = 0; u < 4; u++) a[u] = Qs[ty + 8 * u][k];
#pragma unroll
                for (int j = 0; j < 5; j++) bb[j] = Kt[tx + 32 * j][k];
#pragma unroll
                for (int u = 0; u < 4; u++)
#pragma unroll
                    for (int j = 0; j < 5; j++) acc[u][j] += a[u] * bb[j];
            }
            __syncthreads();
        }
        if (tid < tcnt) dsh[tid] = dloc;
        __syncthreads();
#pragma unroll
        for (int u = 0; u < 4; u++)
#pragma unroll
            for (int j = 0; j < 5; j++) {
                int col = tx + 32 * j;
                if (col < tcnt)
                    wsc[ty + 8 * u][col] = (acc[u][j] + dsh[col]) * SCORE_SCALE;
            }
    }
    __syncthreads();

    // ---- Phase B: per-row exp + L2 renorm -------------------------------
#pragma unroll
    for (int u = 0; u < 4; u++) {
        const int row = ty + 8 * u;
        const int s   = s0 + row;
        const bool valid = (s < S_LEN);
        const int lo = valid ? (max(0, s - BAND) - tlo) : 0;
        const int hi = valid ? (min(S_LEN - 1, s + BAND) - tlo) : -1;

        float m = -3.0e38f;
        for (int j = tx; j < tcnt; j += 32)
            if (j >= lo && j <= hi) m = fmaxf(m, wsc[row][j]);
#pragma unroll
        for (int o = 16; o > 0; o >>= 1) m = fmaxf(m, __shfl_xor_sync(0xffffffffu, m, o));

        float sq = 0.0f;
        for (int j = tx; j < tcnt; j += 32) {
            float e = 0.0f;
            if (j >= lo && j <= hi) {
                e = expf(wsc[row][j] - m);
                sq += e * e;
            }
            wsc[row][j] = e;
        }
#pragma unroll
        for (int o = 16; o > 0; o >>= 1) sq += __shfl_xor_sync(0xffffffffu, sq, o);

        const float inv = (valid && sq > 0.0f) ? (1.0f / sqrtf(sq)) : 0.0f;
        for (int j = tx; j < tcnt; j += 32) wsc[row][j] *= inv;
        __syncwarp();

        if (valid && outA) {
            float* arow = outA + (size_t)(b * S_LEN + s) * S_LEN + tlo;
            for (int j = lo + tx; j <= hi; j += 32) arow[j] = wsc[row][j];
        }
    }
    __syncthreads();

    // ---- Phase C: compound GEMM -----------------------------------------
    {
        float cacc[4][16];
#pragma unroll
        for (int u = 0; u < 4; u++)
#pragma unroll
            for (int j = 0; j < 16; j++) cacc[u][j] = 0.0f;

        for (int tt = 0; tt < tcnt; tt += 4) {
            const int nload = min(4, tcnt - tt);
#pragma unroll
            for (int l = 0; l < 2; l++) {
                int idx = tid + l * 256;
                int row = idx >> 7;
                if (row < nload)
                    ((float4*)vstage)[idx] =
                        ((const float4*)(V + (size_t)(tlo + tt + row) * 512))[idx & 127];
            }
            __syncthreads();
#pragma unroll
            for (int u2 = 0; u2 < 4; u2++) {
                if (u2 >= nload) break;
                float wt[4];
#pragma unroll
                for (int u = 0; u < 4; u++) wt[u] = wsc[ty + 8 * u][tt + u2];
#pragma unroll
                for (int j = 0; j < 16; j++) {
                    float v = vstage[u2 * 512 + tx + 32 * j];
#pragma unroll
                    for (int u = 0; u < 4; u++) cacc[u][j] += wt[u] * v;
                }
            }
            __syncthreads();
        }

        if (outC) {
#pragma unroll
            for (int u = 0; u < 4; u++) {
                const int s = s0 + ty + 8 * u;
                if (s >= S_LEN) continue;
                float* crow = outC + (size_t)(b * S_LEN + s) * DIM;
#pragma unroll
                for (int j = 0; j < 16; j++) crow[tx + 32 * j] = cacc[u][j];
            }
        }
    }
}

// ---------------------------------------------------------------------------
extern "C" void kernel_launch(void* const* d_in, const int* in_sizes, int n_in,
                              void* d_out, int out_size)
{
    const float* x  = (const float*)d_in[0];
    const float* Wq = (const float*)d_in[1];
    const float* bq = (const float*)d_in[2];
    const float* Wk = (const float*)d_in[3];
    // d_in[4] = bk: cancels (per-row-s constant in exp/L2-renorm)
    const float* Wv = (const float*)d_in[5];
    const float* bv = (const float*)d_in[6];

    float* out = (float*)d_out;
    const long long NC = (long long)MROWS * DIM;
    const long long NA = (long long)MROWS * S_LEN;

    float* comp = nullptr;
    float* attn = nullptr;
    if ((long long)out_size >= NC + NA) { comp = out; attn = out + NC; }
    else if ((long long)out_size == NA) { attn = out; }
    else                                { comp = out; }

    if (attn) cudaMemsetAsync(attn, 0, (size_t)NA * sizeof(float), 0);

    prep_w<<<2, 256>>>(Wk, bq);
    wqwk_gemm<<<dim3(4, 4), 256>>>(Wq, Wk);
    qkv_gemm<<<dim3(126, 8), 256>>>(x, Wv, bv);

    dim3 g2((S_LEN + STILE - 1) / STILE, NBATCH);
    band_attn<<<g2, 256>>>(comp, attn, x);
}

// round 8
// speedup vs baseline: 1.3438x; 1.0929x over previous
#include <cuda_runtime.h>
#include <cuda_bf16.h>
#include <math.h>
#include <stdint.h>

#define S_LEN 1001
#define NBATCH 16
#define DIM 512
#define BAND 50
#define MROWS (NBATCH * S_LEN)            // 16016
#define SCORE_SCALE 0.044194173824159216f // 1/sqrt(512)
#define STILE 32
#define TCMAX 136

// Scratch: slice 0 = G = x @ (Wq Wk^T), slice 2 = V. (slice 1 unused)
__device__ float g_QKV[(size_t)3 * MROWS * DIM];
__device__ float g_M[512 * 512];          // Wq @ Wk^T
__device__ float g_w[512];                // Wk @ bq

// ---------------------------------------------------------------------------
__global__ void prep_w(const float* __restrict__ Wk, const float* __restrict__ bq)
{
    const int i = blockIdx.x * 256 + threadIdx.x;
    if (i < 512) {
        float s = 0.0f;
        const float* row = Wk + (size_t)i * 512;
#pragma unroll 8
        for (int d = 0; d < 512; d++) s += row[d] * bq[d];
        g_w[i] = s;
    }
}

// ---------------------------------------------------------------------------
// wqwk_gemm: M = Wq @ Wk^T (fp32; tiny, full precision keeps M exact-ish).
// ---------------------------------------------------------------------------
__global__ __launch_bounds__(256) void wqwk_gemm(const float* __restrict__ Wq,
                                                 const float* __restrict__ Wk)
{
    __shared__ __align__(16) float As[16][128];
    __shared__ __align__(16) float Bs[16][128];

    const int tid = threadIdx.x;
    const int m0  = blockIdx.x * 128;
    const int n0  = blockIdx.y * 128;
    const int tx = tid & 15, ty = tid >> 4;

    float c[8][8];
#pragma unroll
    for (int i = 0; i < 8; i++)
#pragma unroll
        for (int j = 0; j < 8; j++) c[i][j] = 0.0f;

    for (int kk = 0; kk < 512; kk += 16) {
#pragma unroll
        for (int l = 0; l < 2; l++) {
            int fid = tid + l * 256;
            int r = fid >> 2, k4 = (fid & 3) * 4;
            float4 av = *(const float4*)(Wq + (size_t)(m0 + r) * 512 + kk + k4);
            As[k4+0][r] = av.x; As[k4+1][r] = av.y; As[k4+2][r] = av.z; As[k4+3][r] = av.w;
            float4 bv = *(const float4*)(Wk + (size_t)(n0 + r) * 512 + kk + k4);
            Bs[k4+0][r] = bv.x; Bs[k4+1][r] = bv.y; Bs[k4+2][r] = bv.z; Bs[k4+3][r] = bv.w;
        }
        __syncthreads();
#pragma unroll
        for (int k = 0; k < 16; k++) {
            float4 a0 = *(float4*)&As[k][ty * 4];
            float4 a1 = *(float4*)&As[k][64 + ty * 4];
            float4 b0 = *(float4*)&Bs[k][tx * 4];
            float4 b1 = *(float4*)&Bs[k][64 + tx * 4];
            float a[8]  = {a0.x, a0.y, a0.z, a0.w, a1.x, a1.y, a1.z, a1.w};
            float bb[8] = {b0.x, b0.y, b0.z, b0.w, b1.x, b1.y, b1.z, b1.w};
#pragma unroll
            for (int i = 0; i < 8; i++)
#pragma unroll
                for (int j = 0; j < 8; j++) c[i][j] += a[i] * bb[j];
        }
        __syncthreads();
    }
#pragma unroll
    for (int i = 0; i < 8; i++) {
        int lr = (i < 4) ? (ty * 4 + i) : (64 + ty * 4 + (i - 4));
        float* orow = g_M + (size_t)(m0 + lr) * 512 + n0;
        float4 v0 = {c[i][0], c[i][1], c[i][2], c[i][3]};
        float4 v1 = {c[i][4], c[i][5], c[i][6], c[i][7]};
        *(float4*)(orow + tx * 4) = v0;
        *(float4*)(orow + 64 + tx * 4) = v1;
    }
}

// ===========================================================================
// qkv_mma: out = x @ W (+ b) via mma.sync bf16 with 2-term split.
// Grid (126, 8): y>>2 -> 0=G (W=g_M), 1=V (W=Wv, bias). CTA 128x128, BK=32.
// 8 warps = 4(M) x 2(N); warp tile 32x64 = 2 m16 x 8 n8 frags.
// smem: bf16 hi/lo tiles, stride 40 (conflict-free fragment loads).
// ===========================================================================
#define KS 40   // bf16 stride

__device__ __forceinline__ void bf16_split4(float4 v, uint2& hi, uint2& lo) {
    __nv_bfloat16 hx = __float2bfloat16_rn(v.x);
    __nv_bfloat16 hy = __float2bfloat16_rn(v.y);
    __nv_bfloat16 hz = __float2bfloat16_rn(v.z);
    __nv_bfloat16 hw = __float2bfloat16_rn(v.w);
    __nv_bfloat16 lx = __float2bfloat16_rn(v.x - __bfloat162float(hx));
    __nv_bfloat16 ly = __float2bfloat16_rn(v.y - __bfloat162float(hy));
    __nv_bfloat16 lz = __float2bfloat16_rn(v.z - __bfloat162float(hz));
    __nv_bfloat16 lw = __float2bfloat16_rn(v.w - __bfloat162float(hw));
    hi.x = ((uint32_t)__bfloat16_as_ushort(hy) << 16) | __bfloat16_as_ushort(hx);
    hi.y = ((uint32_t)__bfloat16_as_ushort(hw) << 16) | __bfloat16_as_ushort(hz);
    lo.x = ((uint32_t)__bfloat16_as_ushort(ly) << 16) | __bfloat16_as_ushort(lx);
    lo.y = ((uint32_t)__bfloat16_as_ushort(lw) << 16) | __bfloat16_as_ushort(lz);
}

__device__ __forceinline__ void mma16816(float* c, const uint32_t* a, const uint32_t* b) {
    asm volatile(
        "mma.sync.aligned.m16n8k16.row.col.f32.bf16.bf16.f32 "
        "{%0,%1,%2,%3}, {%4,%5,%6,%7}, {%8,%9}, {%0,%1,%2,%3};"
        : "+f"(c[0]), "+f"(c[1]), "+f"(c[2]), "+f"(c[3])
        : "r"(a[0]), "r"(a[1]), "r"(a[2]), "r"(a[3]), "r"(b[0]), "r"(b[1]));
}

__global__ __launch_bounds__(256) void qkv_mma(
    const float* __restrict__ x,
    const float* __restrict__ Wv, const float* __restrict__ bv)
{
    __shared__ __nv_bfloat16 AsH[128][KS], AsL[128][KS];
    __shared__ __nv_bfloat16 BsH[128][KS], BsL[128][KS];

    const int tid  = threadIdx.x;
    const int wid  = tid >> 5;
    const int lane = tid & 31;
    const int m0   = blockIdx.x * 128;
    const int mat  = blockIdx.y >> 2;     // 0=G, 1=V
    const int n0   = (blockIdx.y & 3) * 128;

    const float* __restrict__ W = (mat == 0) ? g_M : Wv;
    float* outp = g_QKV + (size_t)(mat == 0 ? 0 : 2) * MROWS * DIM;

    const int mw = wid >> 1;              // 0..3
    const int nw = wid & 1;               // 0..1
    const int g  = lane >> 2;             // 0..7
    const int tg = lane & 3;              // 0..3

    float acc[2][8][4];
#pragma unroll
    for (int f = 0; f < 2; f++)
#pragma unroll
        for (int nf = 0; nf < 8; nf++)
#pragma unroll
            for (int e = 0; e < 4; e++) acc[f][nf][e] = 0.0f;

    // loader coords
    const int lar = tid >> 1, lac = (tid & 1) * 16;       // A: row, 16-col group
    const int lbk = tid >> 3, lbn = (tid & 7) * 16;       // B: k-row, 16-n group

    for (int c = 0; c < 16; c++) {
        const int k0 = c * 32;
        __syncthreads();
        // ---- A: x[m0+lar][k0+lac .. +16)
#pragma unroll
        for (int j = 0; j < 4; j++) {
            float4 v = make_float4(0.f, 0.f, 0.f, 0.f);
            if (m0 + lar < MROWS)
                v = *(const float4*)(x + (size_t)(m0 + lar) * 512 + k0 + lac + 4 * j);
            uint2 h, l;
            bf16_split4(v, h, l);
            *(uint2*)&AsH[lar][lac + 4 * j] = h;
            *(uint2*)&AsL[lar][lac + 4 * j] = l;
        }
        // ---- B: W[k0+lbk][n0+lbn .. +16) -> Bs[n][k] (transposed)
#pragma unroll
        for (int j = 0; j < 4; j++) {
            float4 v = *(const float4*)(W + (size_t)(k0 + lbk) * 512 + n0 + lbn + 4 * j);
            __nv_bfloat16 h0 = __float2bfloat16_rn(v.x);
            __nv_bfloat16 h1 = __float2bfloat16_rn(v.y);
            __nv_bfloat16 h2 = __float2bfloat16_rn(v.z);
            __nv_bfloat16 h3 = __float2bfloat16_rn(v.w);
            BsH[lbn + 4*j + 0][lbk] = h0;
            BsH[lbn + 4*j + 1][lbk] = h1;
            BsH[lbn + 4*j + 2][lbk] = h2;
            BsH[lbn + 4*j + 3][lbk] = h3;
            BsL[lbn + 4*j + 0][lbk] = __float2bfloat16_rn(v.x - __bfloat162float(h0));
            BsL[lbn + 4*j + 1][lbk] = __float2bfloat16_rn(v.y - __bfloat162float(h1));
            BsL[lbn + 4*j + 2][lbk] = __float2bfloat16_rn(v.z - __bfloat162float(h2));
            BsL[lbn + 4*j + 3][lbk] = __float2bfloat16_rn(v.w - __bfloat162float(h3));
        }
        __syncthreads();

#pragma unroll
        for (int s = 0; s < 2; s++) {
            const int ks = s * 16;
            uint32_t aH[2][4], aL[2][4];
#pragma unroll
            for (int f = 0; f < 2; f++) {
                const int mr = mw * 32 + f * 16;
                aH[f][0] = *(uint32_t*)&AsH[mr + g    ][ks + 2 * tg];
                aH[f][1] = *(uint32_t*)&AsH[mr + g + 8][ks + 2 * tg];
                aH[f][2] = *(uint32_t*)&AsH[mr + g    ][ks + 2 * tg + 8];
                aH[f][3] = *(uint32_t*)&AsH[mr + g + 8][ks + 2 * tg + 8];
                aL[f][0] = *(uint32_t*)&AsL[mr + g    ][ks + 2 * tg];
                aL[f][1] = *(uint32_t*)&AsL[mr + g + 8][ks + 2 * tg];
                aL[f][2] = *(uint32_t*)&AsL[mr + g    ][ks + 2 * tg + 8];
                aL[f][3] = *(uint32_t*)&AsL[mr + g + 8][ks + 2 * tg + 8];
            }
#pragma unroll
            for (int nf = 0; nf < 8; nf++) {
                const int nc = nw * 64 + nf * 8;
                uint32_t bH[2], bL[2];
                bH[0] = *(uint32_t*)&BsH[nc + g][ks + 2 * tg];
                bH[1] = *(uint32_t*)&BsH[nc + g][ks + 2 * tg + 8];
                bL[0] = *(uint32_t*)&BsL[nc + g][ks + 2 * tg];
                bL[1] = *(uint32_t*)&BsL[nc + g][ks + 2 * tg + 8];
#pragma unroll
                for (int f = 0; f < 2; f++) {
                    mma16816(acc[f][nf], aH[f], bH);
                    mma16816(acc[f][nf], aH[f], bL);
                    mma16816(acc[f][nf], aL[f], bH);
                }
            }
        }
    }

    // ---- epilogue: direct stores (+ bias for V) ----
#pragma unroll
    for (int nf = 0; nf < 8; nf++) {
        const int col = n0 + nw * 64 + nf * 8 + 2 * tg;
        float b0 = 0.f, b1 = 0.f;
        if (mat == 1) { b0 = bv[col]; b1 = bv[col + 1]; }
#pragma unroll
        for (int f = 0; f < 2; f++) {
            const int r0 = m0 + mw * 32 + f * 16 + g;
            if (r0 < MROWS) {
                float2 v = {acc[f][nf][0] + b0, acc[f][nf][1] + b1};
                *(float2*)(outp + (size_t)r0 * 512 + col) = v;
            }
            if (r0 + 8 < MROWS) {
                float2 v = {acc[f][nf][2] + b0, acc[f][nf][3] + b1};
                *(float2*)(outp + (size_t)(r0 + 8) * 512 + col) = v;
            }
        }
    }
}

// ---------------------------------------------------------------------------
// Band attention (unchanged from passing R6 version).
// ---------------------------------------------------------------------------
__global__ __launch_bounds__(256) void band_attn(float* __restrict__ outC,
                                                 float* __restrict__ outA,
                                                 const float* __restrict__ x)
{
    __shared__ __align__(16) float Qs[STILE][16];
    __shared__ float Kt[TCMAX][17];
    __shared__ float wsc[STILE][TCMAX];
    __shared__ float dsh[TCMAX];
    __shared__ __align__(16) float vstage[2048];

    const int tid = threadIdx.x;
    const int tx  = tid & 31;
    const int ty  = tid >> 5;
    const int b   = blockIdx.y;
    const int s0  = blockIdx.x * STILE;

    const int tlo  = max(0, s0 - BAND);
    const int thi  = min(S_LEN - 1, s0 + STILE - 1 + BAND);
    const int tcnt = thi - tlo + 1;

    const float* G  = g_QKV + (size_t)(b * S_LEN) * DIM;
    const float* Kx = x + (size_t)(b * S_LEN) * DIM;
    const float* V  = g_QKV + ((size_t)2 * MROWS + b * S_LEN) * DIM;

    {
        float acc[4][5];
#pragma unroll
        for (int u = 0; u < 4; u++)
#pragma unroll
            for (int j = 0; j < 5; j++) acc[u][j] = 0.0f;
        float dloc = 0.0f;

        const int qr = tid >> 3, qk = (tid & 7) * 2;
        for (int kk = 0; kk < 512; kk += 16) {
            *(float2*)&Qs[qr][qk] =
                *(const float2*)(G + (size_t)(s0 + qr) * 512 + kk + qk);
#pragma unroll
            for (int l = 0; l < 5; l++) {
                int idx = tid + l * 256;
                int row = idx >> 3, kq = (idx & 7) * 2;
                if (row < tcnt) {
                    float2 v = *(const float2*)(Kx + (size_t)(tlo + row) * 512 + kk + kq);
                    Kt[row][kq]     = v.x;
                    Kt[row][kq + 1] = v.y;
                }
            }
            __syncthreads();

            if (tid < tcnt) {
#pragma unroll
                for (int k = 0; k < 16; k++) dloc += Kt[tid][k] * g_w[kk + k];
            }
#pragma unroll
            for (int k = 0; k < 16; k++) {
                float a[4], bb[5];
#pragma unroll
                for (int u = 0; u < 4; u++) a[u] = Qs[ty + 8 * u][k];
#pragma unroll
                for (int j = 0; j < 5; j++) bb[j] = Kt[tx + 32 * j][k];
#pragma unroll
                for (int u = 0; u < 4; u++)
#pragma unroll
                    for (int j = 0; j < 5; j++) acc[u][j] += a[u] * bb[j];
            }
            __syncthreads();
        }
        if (tid < tcnt) dsh[tid] = dloc;
        __syncthreads();
#pragma unroll
        for (int u = 0; u < 4; u++)
#pragma unroll
            for (int j = 0; j < 5; j++) {
                int col = tx + 32 * j;
                if (col < tcnt)
                    wsc[ty + 8 * u][col] = (acc[u][j] + dsh[col]) * SCORE_SCALE;
            }
    }
    __syncthreads();

#pragma unroll
    for (int u = 0; u < 4; u++) {
        const int row = ty + 8 * u;
        const int s   = s0 + row;
        const bool valid = (s < S_LEN);
        const int lo = valid ? (max(0, s - BAND) - tlo) : 0;
        const int hi = valid ? (min(S_LEN - 1, s + BAND) - tlo) : -1;

        float m = -3.0e38f;
        for (int j = tx; j < tcnt; j += 32)
            if (j >= lo && j <= hi) m = fmaxf(m, wsc[row][j]);
#pragma unroll
        for (int o = 16; o > 0; o >>= 1) m = fmaxf(m, __shfl_xor_sync(0xffffffffu, m, o));

        float sq = 0.0f;
        for (int j = tx; j < tcnt; j += 32) {
            float e = 0.0f;
            if (j >= lo && j <= hi) {
                e = expf(wsc[row][j] - m);
                sq += e * e;
            }
            wsc[row][j] = e;
        }
#pragma unroll
        for (int o = 16; o > 0; o >>= 1) sq += __shfl_xor_sync(0xffffffffu, sq, o);

        const float inv = (valid && sq > 0.0f) ? (1.0f / sqrtf(sq)) : 0.0f;
        for (int j = tx; j < tcnt; j += 32) wsc[row][j] *= inv;
        __syncwarp();

        if (valid && outA) {
            float* arow = outA + (size_t)(b * S_LEN + s) * S_LEN + tlo;
            for (int j = lo + tx; j <= hi; j += 32) arow[j] = wsc[row][j];
        }
    }
    __syncthreads();

    {
        float cacc[4][16];
#pragma unroll
        for (int u = 0; u < 4; u++)
#pragma unroll
            for (int j = 0; j < 16; j++) cacc[u][j] = 0.0f;

        for (int tt = 0; tt < tcnt; tt += 4) {
            const int nload = min(4, tcnt - tt);
#pragma unroll
            for (int l = 0; l < 2; l++) {
                int idx = tid + l * 256;
                int row = idx >> 7;
                if (row < nload)
                    ((float4*)vstage)[idx] =
                        ((const float4*)(V + (size_t)(tlo + tt + row) * 512))[idx & 127];
            }
            __syncthreads();
#pragma unroll
            for (int u2 = 0; u2 < 4; u2++) {
                if (u2 >= nload) break;
                float wt[4];
#pragma unroll
                for (int u = 0; u < 4; u++) wt[u] = wsc[ty + 8 * u][tt + u2];
#pragma unroll
                for (int j = 0; j < 16; j++) {
                    float v = vstage[u2 * 512 + tx + 32 * j];
#pragma unroll
                    for (int u = 0; u < 4; u++) cacc[u][j] += wt[u] * v;
                }
            }
            __syncthreads();
        }

        if (outC) {
#pragma unroll
            for (int u = 0; u < 4; u++) {
                const int s = s0 + ty + 8 * u;
                if (s >= S_LEN) continue;
                float* crow = outC + (size_t)(b * S_LEN + s) * DIM;
#pragma unroll
                for (int j = 0; j < 16; j++) crow[tx + 32 * j] = cacc[u][j];
            }
        }
    }
}

// ---------------------------------------------------------------------------
extern "C" void kernel_launch(void* const* d_in, const int* in_sizes, int n_in,
                              void* d_out, int out_size)
{
    const float* x  = (const float*)d_in[0];
    const float* Wq = (const float*)d_in[1];
    const float* bq = (const float*)d_in[2];
    const float* Wk = (const float*)d_in[3];
    // d_in[4] = bk: cancels (per-row-s constant in exp/L2-renorm)
    const float* Wv = (const float*)d_in[5];
    const float* bv = (const float*)d_in[6];

    float* out = (float*)d_out;
    const long long NC = (long long)MROWS * DIM;
    const long long NA = (long long)MROWS * S_LEN;

    float* comp = nullptr;
    float* attn = nullptr;
    if ((long long)out_size >= NC + NA) { comp = out; attn = out + NC; }
    else if ((long long)out_size == NA) { attn = out; }
    else                                { comp = out; }

    if (attn) cudaMemsetAsync(attn, 0, (size_t)NA * sizeof(float), 0);

    prep_w<<<2, 256>>>(Wk, bq);
    wqwk_gemm<<<dim3(4, 4), 256>>>(Wq, Wk);
    qkv_mma<<<dim3(126, 8), 256>>>(x, Wv, bv);

    dim3 g2((S_LEN + STILE - 1) / STILE, NBATCH);
    band_attn<<<g2, 256>>>(comp, attn, x);
}

// round 10
// speedup vs baseline: 1.3638x; 1.0149x over previous
#include <cuda_runtime.h>
#include <cuda_bf16.h>
#include <math.h>
#include <stdint.h>

#define S_LEN 1001
#define NBATCH 16
#define DIM 512
#define BAND 50
#define MROWS (NBATCH * S_LEN)            // 16016
#define PADROWS 16128                     // 126*128, loader-safe padding
#define SCORE_SCALE 0.044194173824159216f // 1/sqrt(512)
#define STILE 32
#define TCMAX 136

// fp32 scratch: slice 0 = G = x @ (Wq Wk^T), slice 1 = V
__device__ float g_QKV[(size_t)2 * MROWS * DIM];
__device__ float g_M[512 * 512];          // Wq @ Wk^T
__device__ float g_w[512];                // Wk @ bq
// pre-split bf16 operands
__device__ __nv_bfloat16 g_xh[(size_t)PADROWS * 512];
__device__ __nv_bfloat16 g_xl[(size_t)PADROWS * 512];
__device__ __nv_bfloat16 g_Bh[2 * 512 * 512];   // [mat][n][k], mat 0=M, 1=Wv
__device__ __nv_bfloat16 g_Bl[2 * 512 * 512];

// ---------------------------------------------------------------------------
__global__ void prep_w(const float* __restrict__ Wk, const float* __restrict__ bq)
{
    const int i = blockIdx.x * 256 + threadIdx.x;
    if (i < 512) {
        float s = 0.0f;
        const float* row = Wk + (size_t)i * 512;
#pragma unroll 8
        for (int d = 0; d < 512; d++) s += row[d] * bq[d];
        g_w[i] = s;
    }
}

// ---------------------------------------------------------------------------
// conv_x: split x into bf16 hi/lo; zero-fill padding rows.
// ---------------------------------------------------------------------------
__global__ void conv_x(const float* __restrict__ x)
{
    const size_t i = ((size_t)blockIdx.x * 256 + threadIdx.x) * 4;
    if (i >= (size_t)PADROWS * 512) return;
    float4 v = make_float4(0.f, 0.f, 0.f, 0.f);
    if (i < (size_t)MROWS * 512) v = *(const float4*)(x + i);
    __nv_bfloat16 h[4], l[4];
    float f[4] = {v.x, v.y, v.z, v.w};
#pragma unroll
    for (int j = 0; j < 4; j++) {
        h[j] = __float2bfloat16_rn(f[j]);
        l[j] = __float2bfloat16_rn(f[j] - __bfloat162float(h[j]));
    }
    uint2 ph, pl;
    ph.x = ((uint32_t)__bfloat16_as_ushort(h[1]) << 16) | __bfloat16_as_ushort(h[0]);
    ph.y = ((uint32_t)__bfloat16_as_ushort(h[3]) << 16) | __bfloat16_as_ushort(h[2]);
    pl.x = ((uint32_t)__bfloat16_as_ushort(l[1]) << 16) | __bfloat16_as_ushort(l[0]);
    pl.y = ((uint32_t)__bfloat16_as_ushort(l[3]) << 16) | __bfloat16_as_ushort(l[2]);
    *(uint2*)&g_xh[i] = ph;
    *(uint2*)&g_xl[i] = pl;
}

// ---------------------------------------------------------------------------
// conv_w: transpose+split W[k][n] -> Bt[n][k] bf16 hi/lo. z: 0=g_M, 1=Wv.
// ---------------------------------------------------------------------------
__global__ void conv_w(const float* __restrict__ Wv)
{
    __shared__ float t[32][33];
    const int z  = blockIdx.z;
    const float* __restrict__ W = z ? Wv : g_M;
    const int k0 = blockIdx.x * 32, n0 = blockIdx.y * 32;
    const int tx = threadIdx.x, ty = threadIdx.y;

    for (int r = ty; r < 32; r += 8)
        t[r][tx] = W[(size_t)(k0 + r) * 512 + n0 + tx];
    __syncthreads();
    const size_t base = (size_t)z * 512 * 512;
    for (int r = ty; r < 32; r += 8) {
        float v = t[tx][r];                       // = W[k0+tx][n0+r]
        __nv_bfloat16 h = __float2bfloat16_rn(v);
        g_Bh[base + (size_t)(n0 + r) * 512 + k0 + tx] = h;
        g_Bl[base + (size_t)(n0 + r) * 512 + k0 + tx] =
            __float2bfloat16_rn(v - __bfloat162float(h));
    }
}

// ---------------------------------------------------------------------------
// wqwk_gemm: M = Wq @ Wk^T (fp32).
// ---------------------------------------------------------------------------
__global__ __launch_bounds__(256) void wqwk_gemm(const float* __restrict__ Wq,
                                                 const float* __restrict__ Wk)
{
    __shared__ __align__(16) float As[16][128];
    __shared__ __align__(16) float Bs[16][128];

    const int tid = threadIdx.x;
    const int m0  = blockIdx.x * 128;
    const int n0  = blockIdx.y * 128;
    const int tx = tid & 15, ty = tid >> 4;

    float c[8][8];
#pragma unroll
    for (int i = 0; i < 8; i++)
#pragma unroll
        for (int j = 0; j < 8; j++) c[i][j] = 0.0f;

    for (int kk = 0; kk < 512; kk += 16) {
#pragma unroll
        for (int l = 0; l < 2; l++) {
            int fid = tid + l * 256;
            int r = fid >> 2, k4 = (fid & 3) * 4;
            float4 av = *(const float4*)(Wq + (size_t)(m0 + r) * 512 + kk + k4);
            As[k4+0][r] = av.x; As[k4+1][r] = av.y; As[k4+2][r] = av.z; As[k4+3][r] = av.w;
            float4 bv = *(const float4*)(Wk + (size_t)(n0 + r) * 512 + kk + k4);
            Bs[k4+0][r] = bv.x; Bs[k4+1][r] = bv.y; Bs[k4+2][r] = bv.z; Bs[k4+3][r] = bv.w;
        }
        __syncthreads();
#pragma unroll
        for (int k = 0; k < 16; k++) {
            float4 a0 = *(float4*)&As[k][ty * 4];
            float4 a1 = *(float4*)&As[k][64 + ty * 4];
            float4 b0 = *(float4*)&Bs[k][tx * 4];
            float4 b1 = *(float4*)&Bs[k][64 + tx * 4];
            float a[8]  = {a0.x, a0.y, a0.z, a0.w, a1.x, a1.y, a1.z, a1.w};
            float bb[8] = {b0.x, b0.y, b0.z, b0.w, b1.x, b1.y, b1.z, b1.w};
#pragma unroll
            for (int i = 0; i < 8; i++)
#pragma unroll
                for (int j = 0; j < 8; j++) c[i][j] += a[i] * bb[j];
        }
        __syncthreads();
    }
#pragma unroll
    for (int i = 0; i < 8; i++) {
        int lr = (i < 4) ? (ty * 4 + i) : (64 + ty * 4 + (i - 4));
        float* orow = g_M + (size_t)(m0 + lr) * 512 + n0;
        float4 v0 = {c[i][0], c[i][1], c[i][2], c[i][3]};
        float4 v1 = {c[i][4], c[i][5], c[i][6], c[i][7]};
        *(float4*)(orow + tx * 4) = v0;
        *(float4*)(orow + 64 + tx * 4) = v1;
    }
}

// ===========================================================================
// qkv_mma: out = x @ W (+ b) via mma.sync bf16 2-term split, operands
// pre-split in gmem. Pure LDG.128->STS.128 loader, stride-40 smem.
// Grid (126, 8): y>>2 -> 0=G, 1=V. CTA 128x128, BK=32.
// ===========================================================================
#define KS 40

__device__ __forceinline__ void mma16816(float* c, const uint32_t* a, const uint32_t* b) {
    asm volatile(
        "mma.sync.aligned.m16n8k16.row.col.f32.bf16.bf16.f32 "
        "{%0,%1,%2,%3}, {%4,%5,%6,%7}, {%8,%9}, {%0,%1,%2,%3};"
        : "+f"(c[0]), "+f"(c[1]), "+f"(c[2]), "+f"(c[3])
        : "r"(a[0]), "r"(a[1]), "r"(a[2]), "r"(a[3]), "r"(b[0]), "r"(b[1]));
}

__global__ __launch_bounds__(256) void qkv_mma(const float* __restrict__ bv)
{
    __shared__ __nv_bfloat16 AsH[128][KS], AsL[128][KS];
    __shared__ __nv_bfloat16 BsH[128][KS], BsL[128][KS];

    const int tid  = threadIdx.x;
    const int wid  = tid >> 5;
    const int lane = tid & 31;
    const int m0   = blockIdx.x * 128;
    const int mat  = blockIdx.y >> 2;     // 0=G, 1=V
    const int n0   = (blockIdx.y & 3) * 128;

    const size_t boff = (size_t)mat * 512 * 512;
    float* outp = g_QKV + (size_t)mat * MROWS * DIM;

    const int mw = wid >> 1;
    const int nw = wid & 1;
    const int g  = lane >> 2;
    const int tg = lane & 3;

    float acc[2][8][4];
#pragma unroll
    for (int f = 0; f < 2; f++)
#pragma unroll
        for (int nf = 0; nf < 8; nf++)
#pragma unroll
            for (int e = 0; e < 4; e++) acc[f][nf][e] = 0.0f;

    const int lar = tid >> 1;             // 0..127
    const int lac = (tid & 1) * 16;       // 0 or 16

    const __nv_bfloat16* __restrict__ srcAH = g_xh + (size_t)(m0 + lar) * 512;
    const __nv_bfloat16* __restrict__ srcAL = g_xl + (size_t)(m0 + lar) * 512;
    const __nv_bfloat16* __restrict__ srcBH = g_Bh + boff + (size_t)(n0 + lar) * 512;
    const __nv_bfloat16* __restrict__ srcBL = g_Bl + boff + (size_t)(n0 + lar) * 512;

    for (int c = 0; c < 16; c++) {
        const int k0 = c * 32;
        __syncthreads();
#pragma unroll
        for (int j = 0; j < 2; j++) {
            const int col = lac + 8 * j;
            *(uint4*)&AsH[lar][col] = *(const uint4*)(srcAH + k0 + col);
            *(uint4*)&AsL[lar][col] = *(const uint4*)(srcAL + k0 + col);
            *(uint4*)&BsH[lar][col] = *(const uint4*)(srcBH + k0 + col);
            *(uint4*)&BsL[lar][col] = *(const uint4*)(srcBL + k0 + col);
        }
        __syncthreads();

#pragma unroll
        for (int s = 0; s < 2; s++) {
            const int ks = s * 16;
            uint32_t aH[2][4], aL[2][4];
#pragma unroll
            for (int f = 0; f < 2; f++) {
                const int mr = mw * 32 + f * 16;
                aH[f][0] = *(uint32_t*)&AsH[mr + g    ][ks + 2 * tg];
                aH[f][1] = *(uint32_t*)&AsH[mr + g + 8][ks + 2 * tg];
                aH[f][2] = *(uint32_t*)&AsH[mr + g    ][ks + 2 * tg + 8];
                aH[f][3] = *(uint32_t*)&AsH[mr + g + 8][ks + 2 * tg + 8];
                aL[f][0] = *(uint32_t*)&AsL[mr + g    ][ks + 2 * tg];
                aL[f][1] = *(uint32_t*)&AsL[mr + g + 8][ks + 2 * tg];
                aL[f][2] = *(uint32_t*)&AsL[mr + g    ][ks + 2 * tg + 8];
                aL[f][3] = *(uint32_t*)&AsL[mr + g + 8][ks + 2 * tg + 8];
            }
#pragma unroll
            for (int nf = 0; nf < 8; nf++) {
                const int nc = nw * 64 + nf * 8;
                uint32_t bH[2], bL[2];
                bH[0] = *(uint32_t*)&BsH[nc + g][ks + 2 * tg];
                bH[1] = *(uint32_t*)&BsH[nc + g][ks + 2 * tg + 8];
                bL[0] = *(uint32_t*)&BsL[nc + g][ks + 2 * tg];
                bL[1] = *(uint32_t*)&BsL[nc + g][ks + 2 * tg + 8];
#pragma unroll
                for (int f = 0; f < 2; f++) {
                    mma16816(acc[f][nf], aH[f], bH);
                    mma16816(acc[f][nf], aH[f], bL);
                    mma16816(acc[f][nf], aL[f], bH);
                }
            }
        }
    }

    // ---- epilogue: direct stores (+ bias for V) ----
#pragma unroll
    for (int nf = 0; nf < 8; nf++) {
        const int col = n0 + nw * 64 + nf * 8 + 2 * tg;
        float b0 = 0.f, b1 = 0.f;
        if (mat == 1) { b0 = bv[col]; b1 = bv[col + 1]; }
#pragma unroll
        for (int f = 0; f < 2; f++) {
            const int r0 = m0 + mw * 32 + f * 16 + g;
            if (r0 < MROWS) {
                float2 v = {acc[f][nf][0] + b0, acc[f][nf][1] + b1};
                *(float2*)(outp + (size_t)r0 * 512 + col) = v;
            }
            if (r0 + 8 < MROWS) {
                float2 v = {acc[f][nf][2] + b0, acc[f][nf][3] + b1};
                *(float2*)(outp + (size_t)(r0 + 8) * 512 + col) = v;
            }
        }
    }
}

// ---------------------------------------------------------------------------
// Band attention. Phase C runs as two 256-col half-passes (fewer regs).
// ---------------------------------------------------------------------------
__global__ __launch_bounds__(256) void band_attn(float* __restrict__ outC,
                                                 float* __restrict__ outA,
                                                 const float* __restrict__ x)
{
    __shared__ __align__(16) float Qs[STILE][16];
    __shared__ float Kt[TCMAX][17];
    __shared__ float wsc[STILE][TCMAX];
    __shared__ float dsh[TCMAX];
    __shared__ __align__(16) float vstage[1024];   // 4 rows x 256 cols

    const int tid = threadIdx.x;
    const int tx  = tid & 31;
    const int ty  = tid >> 5;
    const int b   = blockIdx.y;
    const int s0  = blockIdx.x * STILE;

    const int tlo  = max(0, s0 - BAND);
    const int thi  = min(S_LEN - 1, s0 + STILE - 1 + BAND);
    const int tcnt = thi - tlo + 1;

    const float* G  = g_QKV + (size_t)(b * S_LEN) * DIM;
    const float* Kx = x + (size_t)(b * S_LEN) * DIM;
    const float* V  = g_QKV + ((size_t)MROWS + b * S_LEN) * DIM;

    // ---- Phase A: scores GEMM + d_t ------------------------------------
    {
        float acc[4][5];
#pragma unroll
        for (int u = 0; u < 4; u++)
#pragma unroll
            for (int j = 0; j < 5; j++) acc[u][j] = 0.0f;
        float dloc = 0.0f;

        const int qr = tid >> 3, qk = (tid & 7) * 2;
        for (int kk = 0; kk < 512; kk += 16) {
            *(float2*)&Qs[qr][qk] =
                *(const float2*)(G + (size_t)(s0 + qr) * 512 + kk + qk);
#pragma unroll
            for (int l = 0; l < 5; l++) {
                int idx = tid + l * 256;
                int row = idx >> 3, kq = (idx & 7) * 2;
                if (row < tcnt) {
                    float2 v = *(const float2*)(Kx + (size_t)(tlo + row) * 512 + kk + kq);
                    Kt[row][kq]     = v.x;
                    Kt[row][kq + 1] = v.y;
                }
            }
            __syncthreads();

            if (tid < tcnt) {
#pragma unroll
                for (int k = 0; k < 16; k++) dloc += Kt[tid][k] * g_w[kk + k];
            }
#pragma unroll
            for (int k = 0; k < 16; k++) {
                float a[4], bb[5];
#pragma unroll
                for (int u = 0; u < 4; u++) a[u] = Qs[ty + 8 * u][k];
#pragma unroll
                for (int j = 0; j < 5; j++) bb[j] = Kt[tx + 32 * j][k];
#pragma unroll
                for (int u = 0; u < 4; u++)
#pragma unroll
                    for (int j = 0; j < 5; j++) acc[u][j] += a[u] * bb[j];
            }
            __syncthreads();
        }
        if (tid < tcnt) dsh[tid] = dloc;
        __syncthreads();
#pragma unroll
        for (int u = 0; u < 4; u++)
#pragma unroll
            for (int j = 0; j < 5; j++) {
                int col = tx + 32 * j;
                if (col < tcnt)
                    wsc[ty + 8 * u][col] = (acc[u][j] + dsh[col]) * SCORE_SCALE;
            }
    }
    __syncthreads();

    // ---- Phase B: per-row exp + L2 renorm -------------------------------
#pragma unroll
    for (int u = 0; u < 4; u++) {
        const int row = ty + 8 * u;
        const int s   = s0 + row;
        const bool valid = (s < S_LEN);
        const int lo = valid ? (max(0, s - BAND) - tlo) : 0;
        const int hi = valid ? (min(S_LEN - 1, s + BAND) - tlo) : -1;

        float m = -3.0e38f;
        for (int j = tx; j < tcnt; j += 32)
            if (j >= lo && j <= hi) m = fmaxf(m, wsc[row][j]);
#pragma unroll
        for (int o = 16; o > 0; o >>= 1) m = fmaxf(m, __shfl_xor_sync(0xffffffffu, m, o));

        float sq = 0.0f;
        for (int j = tx; j < tcnt; j += 32) {
            float e = 0.0f;
            if (j >= lo && j <= hi) {
                e = expf(wsc[row][j] - m);
                sq += e * e;
            }
            wsc[row][j] = e;
        }
#pragma unroll
        for (int o = 16; o > 0; o >>= 1) sq += __shfl_xor_sync(0xffffffffu, sq, o);

        const float inv = (valid && sq > 0.0f) ? (1.0f / sqrtf(sq)) : 0.0f;
        for (int j = tx; j < tcnt; j += 32) wsc[row][j] *= inv;
        __syncwarp();

        if (valid && outA) {
            float* arow = outA + (size_t)(b * S_LEN + s) * S_LEN + tlo;
            for (int j = lo + tx; j <= hi; j += 32) arow[j] = wsc[row][j];
        }
    }
    __syncthreads();

    // ---- Phase C: compound GEMM, two 256-col halves ---------------------
#pragma unroll 1
    for (int half = 0; half < 2; half++) {
        const int c0 = half * 256;
        float cacc[4][8];
#pragma unroll
        for (int u = 0; u < 4; u++)
#pragma unroll
            for (int j = 0; j < 8; j++) cacc[u][j] = 0.0f;

        for (int tt = 0; tt < tcnt; tt += 4) {
            const int nload = min(4, tcnt - tt);
            {
                const int row = tid >> 6;             // 0..3
                if (row < nload)
                    ((float4*)vstage)[tid] =
                        *(const float4*)(V + (size_t)(tlo + tt + row) * 512 + c0 + (tid & 63) * 4);
            }
            __syncthreads();
#pragma unroll
            for (int u2 = 0; u2 < 4; u2++) {
                if (u2 >= nload) break;
                float wt[4];
#pragma unroll
                for (int u = 0; u < 4; u++) wt[u] = wsc[ty + 8 * u][tt + u2];
#pragma unroll
                for (int j = 0; j < 8; j++) {
                    float v = vstage[u2 * 256 + tx + 32 * j];
#pragma unroll
                    for (int u = 0; u < 4; u++) cacc[u][j] += wt[u] * v;
                }
            }
            __syncthreads();
        }

        if (outC) {
#pragma unroll
            for (int u = 0; u < 4; u++) {
                const int s = s0 + ty + 8 * u;
                if (s >= S_LEN) continue;
                float* crow = outC + (size_t)(b * S_LEN + s) * DIM + c0;
#pragma unroll
                for (int j = 0; j < 8; j++) crow[tx + 32 * j] = cacc[u][j];
            }
        }
    }
}

// ---------------------------------------------------------------------------
extern "C" void kernel_launch(void* const* d_in, const int* in_sizes, int n_in,
                              void* d_out, int out_size)
{
    const float* x  = (const float*)d_in[0];
    const float* Wq = (const float*)d_in[1];
    const float* bq = (const float*)d_in[2];
    const float* Wk = (const float*)d_in[3];
    // d_in[4] = bk: cancels (per-row-s constant in exp/L2-renorm)
    const float* Wv = (const float*)d_in[5];
    const float* bv = (const float*)d_in[6];

    float* out = (float*)d_out;
    const long long NC = (long long)MROWS * DIM;
    const long long NA = (long long)MROWS * S_LEN;

    float* comp = nullptr;
    float* attn = nullptr;
    if ((long long)out_size >= NC + NA) { comp = out; attn = out + NC; }
    else if ((long long)out_size == NA) { attn = out; }
    else                                { comp = out; }

    if (attn) cudaMemsetAsync(attn, 0, (size_t)NA * sizeof(float), 0);

    conv_x<<<(PADROWS * 512 / 4 + 255) / 256, 256>>>(x);
    prep_w<<<2, 256>>>(Wk, bq);
    wqwk_gemm<<<dim3(4, 4), 256>>>(Wq, Wk);
    conv_w<<<dim3(16, 16, 2), dim3(32, 8)>>>(Wv);
    qkv_mma<<<dim3(126, 8), 256>>>(bv);

    dim3 g2((S_LEN + STILE - 1) / STILE, NBATCH);
    band_attn<<<g2, 256>>>(comp, attn, x);
}

// round 11
// speedup vs baseline: 1.4451x; 1.0596x over previous
#include <cuda_runtime.h>
#include <cuda_bf16.h>
#include <math.h>
#include <stdint.h>

#define S_LEN 1001
#define NBATCH 16
#define DIM 512
#define BAND 50
#define MROWS (NBATCH * S_LEN)            // 16016
#define PADROWS 16128                     // 126*128, loader-safe padding
#define SCORE_SCALE 0.044194173824159216f // 1/sqrt(512)
#define STILE 32
#define TCMAX 136

// fp32 scratch: slice 0 = G = x @ (Wq Wk^T), slice 1 = V
__device__ float g_QKV[(size_t)2 * MROWS * DIM];
__device__ float g_M[512 * 512];          // Wq @ Wk^T
__device__ float g_w[512];                // Wk @ bq
// pre-split bf16 operands
__device__ __nv_bfloat16 g_xh[(size_t)PADROWS * 512];
__device__ __nv_bfloat16 g_xl[(size_t)PADROWS * 512];
__device__ __nv_bfloat16 g_Bh[2 * 512 * 512];   // [mat][n][k], mat 0=M, 1=Wv
__device__ __nv_bfloat16 g_Bl[2 * 512 * 512];

// ---------------------------------------------------------------------------
__global__ void prep_w(const float* __restrict__ Wk, const float* __restrict__ bq)
{
    const int i = blockIdx.x * 256 + threadIdx.x;
    if (i < 512) {
        float s = 0.0f;
        const float* row = Wk + (size_t)i * 512;
#pragma unroll 8
        for (int d = 0; d < 512; d++) s += row[d] * bq[d];
        g_w[i] = s;
    }
}

// ---------------------------------------------------------------------------
__global__ void conv_x(const float* __restrict__ x)
{
    const size_t i = ((size_t)blockIdx.x * 256 + threadIdx.x) * 4;
    if (i >= (size_t)PADROWS * 512) return;
    float4 v = make_float4(0.f, 0.f, 0.f, 0.f);
    if (i < (size_t)MROWS * 512) v = *(const float4*)(x + i);
    __nv_bfloat16 h[4], l[4];
    float f[4] = {v.x, v.y, v.z, v.w};
#pragma unroll
    for (int j = 0; j < 4; j++) {
        h[j] = __float2bfloat16_rn(f[j]);
        l[j] = __float2bfloat16_rn(f[j] - __bfloat162float(h[j]));
    }
    uint2 ph, pl;
    ph.x = ((uint32_t)__bfloat16_as_ushort(h[1]) << 16) | __bfloat16_as_ushort(h[0]);
    ph.y = ((uint32_t)__bfloat16_as_ushort(h[3]) << 16) | __bfloat16_as_ushort(h[2]);
    pl.x = ((uint32_t)__bfloat16_as_ushort(l[1]) << 16) | __bfloat16_as_ushort(l[0]);
    pl.y = ((uint32_t)__bfloat16_as_ushort(l[3]) << 16) | __bfloat16_as_ushort(l[2]);
    *(uint2*)&g_xh[i] = ph;
    *(uint2*)&g_xl[i] = pl;
}

// ---------------------------------------------------------------------------
__global__ void conv_w(const float* __restrict__ Wv)
{
    __shared__ float t[32][33];
    const int z  = blockIdx.z;
    const float* __restrict__ W = z ? Wv : g_M;
    const int k0 = blockIdx.x * 32, n0 = blockIdx.y * 32;
    const int tx = threadIdx.x, ty = threadIdx.y;

    for (int r = ty; r < 32; r += 8)
        t[r][tx] = W[(size_t)(k0 + r) * 512 + n0 + tx];
    __syncthreads();
    const size_t base = (size_t)z * 512 * 512;
    for (int r = ty; r < 32; r += 8) {
        float v = t[tx][r];                       // = W[k0+tx][n0+r]
        __nv_bfloat16 h = __float2bfloat16_rn(v);
        g_Bh[base + (size_t)(n0 + r) * 512 + k0 + tx] = h;
        g_Bl[base + (size_t)(n0 + r) * 512 + k0 + tx] =
            __float2bfloat16_rn(v - __bfloat162float(h));
    }
}

// ---------------------------------------------------------------------------
// wqwk_gemm: M = Wq @ Wk^T (fp32).
// ---------------------------------------------------------------------------
__global__ __launch_bounds__(256) void wqwk_gemm(const float* __restrict__ Wq,
                                                 const float* __restrict__ Wk)
{
    __shared__ __align__(16) float As[16][128];
    __shared__ __align__(16) float Bs[16][128];

    const int tid = threadIdx.x;
    const int m0  = blockIdx.x * 128;
    const int n0  = blockIdx.y * 128;
    const int tx = tid & 15, ty = tid >> 4;

    float c[8][8];
#pragma unroll
    for (int i = 0; i < 8; i++)
#pragma unroll
        for (int j = 0; j < 8; j++) c[i][j] = 0.0f;

    for (int kk = 0; kk < 512; kk += 16) {
#pragma unroll
        for (int l = 0; l < 2; l++) {
            int fid = tid + l * 256;
            int r = fid >> 2, k4 = (fid & 3) * 4;
            float4 av = *(const float4*)(Wq + (size_t)(m0 + r) * 512 + kk + k4);
            As[k4+0][r] = av.x; As[k4+1][r] = av.y; As[k4+2][r] = av.z; As[k4+3][r] = av.w;
            float4 bv = *(const float4*)(Wk + (size_t)(n0 + r) * 512 + kk + k4);
            Bs[k4+0][r] = bv.x; Bs[k4+1][r] = bv.y; Bs[k4+2][r] = bv.z; Bs[k4+3][r] = bv.w;
        }
        __syncthreads();
#pragma unroll
        for (int k = 0; k < 16; k++) {
            float4 a0 = *(float4*)&As[k][ty * 4];
            float4 a1 = *(float4*)&As[k][64 + ty * 4];
            float4 b0 = *(float4*)&Bs[k][tx * 4];
            float4 b1 = *(float4*)&Bs[k][64 + tx * 4];
            float a[8]  = {a0.x, a0.y, a0.z, a0.w, a1.x, a1.y, a1.z, a1.w};
            float bb[8] = {b0.x, b0.y, b0.z, b0.w, b1.x, b1.y, b1.z, b1.w};
#pragma unroll
            for (int i = 0; i < 8; i++)
#pragma unroll
                for (int j = 0; j < 8; j++) c[i][j] += a[i] * bb[j];
        }
        __syncthreads();
    }
#pragma unroll
    for (int i = 0; i < 8; i++) {
        int lr = (i < 4) ? (ty * 4 + i) : (64 + ty * 4 + (i - 4));
        float* orow = g_M + (size_t)(m0 + lr) * 512 + n0;
        float4 v0 = {c[i][0], c[i][1], c[i][2], c[i][3]};
        float4 v1 = {c[i][4], c[i][5], c[i][6], c[i][7]};
        *(float4*)(orow + tx * 4) = v0;
        *(float4*)(orow + 64 + tx * 4) = v1;
    }
}

// ===========================================================================
// qkv_mma: out = x @ W (+ b), mma.sync bf16 2-term split, ldmatrix.x4 feeds,
// cp.async double-buffered smem (one barrier per chunk).
// Grid (126, 8): y>>2 -> 0=G, 1=V. CTA 128x128, BK=32, stride-40 smem rows.
// ===========================================================================
#define KS 40
#define ARR_BYTES (128 * KS * 2)      // 10240
#define BUF_BYTES (4 * ARR_BYTES)     // 40960
#define QKV_SMEM  (2 * BUF_BYTES)     // 81920

__device__ __forceinline__ void mma16816(float* c, const uint32_t* a, const uint32_t* b) {
    asm volatile(
        "mma.sync.aligned.m16n8k16.row.col.f32.bf16.bf16.f32 "
        "{%0,%1,%2,%3}, {%4,%5,%6,%7}, {%8,%9}, {%0,%1,%2,%3};"
        : "+f"(c[0]), "+f"(c[1]), "+f"(c[2]), "+f"(c[3])
        : "r"(a[0]), "r"(a[1]), "r"(a[2]), "r"(a[3]), "r"(b[0]), "r"(b[1]));
}
__device__ __forceinline__ void ldsm4(uint32_t* r, uint32_t addr) {
    asm volatile("ldmatrix.sync.aligned.m8n8.x4.shared.b16 {%0,%1,%2,%3}, [%4];"
                 : "=r"(r[0]), "=r"(r[1]), "=r"(r[2]), "=r"(r[3]) : "r"(addr));
}
__device__ __forceinline__ void cp16(uint32_t dst, const void* src) {
    asm volatile("cp.async.cg.shared.global [%0], [%1], 16;"
                 :: "r"(dst), "l"(src) : "memory");
}

__global__ __launch_bounds__(256) void qkv_mma(const float* __restrict__ bv)
{
    extern __shared__ char dynsmem[];
    const int tid  = threadIdx.x;
    const int wid  = tid >> 5;
    const int lane = tid & 31;
    const int m0   = blockIdx.x * 128;
    const int mat  = blockIdx.y >> 2;     // 0=G, 1=V
    const int n0   = (blockIdx.y & 3) * 128;

    const size_t boff = (size_t)mat * 512 * 512;
    float* outp = g_QKV + (size_t)mat * MROWS * DIM;

    const int mw = wid >> 1;
    const int nw = wid & 1;
    const int g  = lane >> 2;
    const int tg = lane & 3;

    const uint32_t sbase = (uint32_t)__cvta_generic_to_shared(dynsmem);

    float acc[2][8][4];
#pragma unroll
    for (int f = 0; f < 2; f++)
#pragma unroll
        for (int nf = 0; nf < 8; nf++)
#pragma unroll
            for (int e = 0; e < 4; e++) acc[f][nf][e] = 0.0f;

    // ---- loader coords: 8 x cp.async(16B) per thread per chunk ----
    const int lar = tid >> 1;             // 0..127
    const int lac = (tid & 1) * 16;       // 0 or 16
    const __nv_bfloat16* __restrict__ srcAH = g_xh + (size_t)(m0 + lar) * 512;
    const __nv_bfloat16* __restrict__ srcAL = g_xl + (size_t)(m0 + lar) * 512;
    const __nv_bfloat16* __restrict__ srcBH = g_Bh + boff + (size_t)(n0 + lar) * 512;
    const __nv_bfloat16* __restrict__ srcBL = g_Bl + boff + (size_t)(n0 + lar) * 512;
    const uint32_t dstrow = (uint32_t)(lar * KS) * 2;

    // ---- ldmatrix per-thread offsets ----
    const uint32_t aoff = (uint32_t)((mw * 32 + (lane & 15)) * KS + (lane >> 4) * 8) * 2;
    const int browoff = ((lane >> 4) << 3) + (lane & 7);
    const int bcol8   = ((lane >> 3) & 1) * 8;
    const uint32_t boffm = (uint32_t)((nw * 64 + browoff) * KS + bcol8) * 2;

    // ---- prologue: prefetch chunk 0 into buffer 0 ----
    {
        const uint32_t d = sbase;
#pragma unroll
        for (int j = 0; j < 2; j++) {
            const int col = lac + 8 * j;
            const uint32_t cb = dstrow + (uint32_t)col * 2;
            cp16(d + 0 * ARR_BYTES + cb, srcAH + col);
            cp16(d + 1 * ARR_BYTES + cb, srcAL + col);
            cp16(d + 2 * ARR_BYTES + cb, srcBH + col);
            cp16(d + 3 * ARR_BYTES + cb, srcBL + col);
        }
        asm volatile("cp.async.commit_group;" ::: "memory");
    }

    for (int c = 0; c < 16; c++) {
        const int buf = c & 1;
        asm volatile("cp.async.wait_group 0;" ::: "memory");
        __syncthreads();

        if (c < 15) {   // prefetch chunk c+1 into the other buffer
            const int k0n = (c + 1) * 32;
            const uint32_t d = sbase + (buf ^ 1) * BUF_BYTES;
#pragma unroll
            for (int j = 0; j < 2; j++) {
                const int col = lac + 8 * j;
                const uint32_t cb = dstrow + (uint32_t)col * 2;
                cp16(d + 0 * ARR_BYTES + cb, srcAH + k0n + col);
                cp16(d + 1 * ARR_BYTES + cb, srcAL + k0n + col);
                cp16(d + 2 * ARR_BYTES + cb, srcBH + k0n + col);
                cp16(d + 3 * ARR_BYTES + cb, srcBL + k0n + col);
            }
            asm volatile("cp.async.commit_group;" ::: "memory");
        }

        // ---- compute on buffer buf ----
        const uint32_t base = sbase + buf * BUF_BYTES;
        const uint32_t aH0 = base + 0 * ARR_BYTES + aoff;
        const uint32_t aL0 = base + 1 * ARR_BYTES + aoff;
        const uint32_t bH0 = base + 2 * ARR_BYTES + boffm;
        const uint32_t bL0 = base + 3 * ARR_BYTES + boffm;

#pragma unroll
        for (int s = 0; s < 2; s++) {
            const uint32_t so = (uint32_t)s * 32;   // 16 cols * 2B
            uint32_t aH[2][4], aL[2][4];
            ldsm4(aH[0], aH0 + so);
            ldsm4(aH[1], aH0 + 16 * KS * 2 + so);
            ldsm4(aL[0], aL0 + so);
            ldsm4(aL[1], aL0 + 16 * KS * 2 + so);
#pragma unroll
            for (int p = 0; p < 4; p++) {
                uint32_t bh[4], bl[4];
                ldsm4(bh, bH0 + p * (16 * KS * 2) + so);
                ldsm4(bl, bL0 + p * (16 * KS * 2) + so);
#pragma unroll
                for (int f = 0; f < 2; f++) {
                    mma16816(acc[f][2 * p],     aH[f], bh);
                    mma16816(acc[f][2 * p],     aH[f], bl);
                    mma16816(acc[f][2 * p],     aL[f], bh);
                    mma16816(acc[f][2 * p + 1], aH[f], bh + 2);
                    mma16816(acc[f][2 * p + 1], aH[f], bl + 2);
                    mma16816(acc[f][2 * p + 1], aL[f], bh + 2);
                }
            }
        }
    }

    // ---- epilogue: direct stores (+ bias for V) ----
#pragma unroll
    for (int nf = 0; nf < 8; nf++) {
        const int col = n0 + nw * 64 + nf * 8 + 2 * tg;
        float b0 = 0.f, b1 = 0.f;
        if (mat == 1) { b0 = bv[col]; b1 = bv[col + 1]; }
#pragma unroll
        for (int f = 0; f < 2; f++) {
            const int r0 = m0 + mw * 32 + f * 16 + g;
            if (r0 < MROWS) {
                float2 v = {acc[f][nf][0] + b0, acc[f][nf][1] + b1};
                *(float2*)(outp + (size_t)r0 * 512 + col) = v;
            }
            if (r0 + 8 < MROWS) {
                float2 v = {acc[f][nf][2] + b0, acc[f][nf][3] + b1};
                *(float2*)(outp + (size_t)(r0 + 8) * 512 + col) = v;
            }
        }
    }
}

// ---------------------------------------------------------------------------
// Band attention (unchanged from passing R10 version).
// ---------------------------------------------------------------------------
__global__ __launch_bounds__(256) void band_attn(float* __restrict__ outC,
                                                 float* __restrict__ outA,
                                                 const float* __restrict__ x)
{
    __shared__ __align__(16) float Qs[STILE][16];
    __shared__ float Kt[TCMAX][17];
    __shared__ float wsc[STILE][TCMAX];
    __shared__ float dsh[TCMAX];
    __shared__ __align__(16) float vstage[1024];   // 4 rows x 256 cols

    const int tid = threadIdx.x;
    const int tx  = tid & 31;
    const int ty  = tid >> 5;
    const int b   = blockIdx.y;
    const int s0  = blockIdx.x * STILE;

    const int tlo  = max(0, s0 - BAND);
    const int thi  = min(S_LEN - 1, s0 + STILE - 1 + BAND);
    const int tcnt = thi - tlo + 1;

    const float* G  = g_QKV + (size_t)(b * S_LEN) * DIM;
    const float* Kx = x + (size_t)(b * S_LEN) * DIM;
    const float* V  = g_QKV + ((size_t)MROWS + b * S_LEN) * DIM;

    // ---- Phase A: scores GEMM + d_t ------------------------------------
    {
        float acc[4][5];
#pragma unroll
        for (int u = 0; u < 4; u++)
#pragma unroll
            for (int j = 0; j < 5; j++) acc[u][j] = 0.0f;
        float dloc = 0.0f;

        const int qr = tid >> 3, qk = (tid & 7) * 2;
        for (int kk = 0; kk < 512; kk += 16) {
            *(float2*)&Qs[qr][qk] =
                *(const float2*)(G + (size_t)(s0 + qr) * 512 + kk + qk);
#pragma unroll
            for (int l = 0; l < 5; l++) {
                int idx = tid + l * 256;
                int row = idx >> 3, kq = (idx & 7) * 2;
                if (row < tcnt) {
                    float2 v = *(const float2*)(Kx + (size_t)(tlo + row) * 512 + kk + kq);
                    Kt[row][kq]     = v.x;
                    Kt[row][kq + 1] = v.y;
                }
            }
            __syncthreads();

            if (tid < tcnt) {
#pragma unroll
                for (int k = 0; k < 16; k++) dloc += Kt[tid][k] * g_w[kk + k];
            }
#pragma unroll
            for (int k = 0; k < 16; k++) {
                float a[4], bb[5];
#pragma unroll
                for (int u = 0; u < 4; u++) a[u] = Qs[ty + 8 * u][k];
#pragma unroll
                for (int j = 0; j < 5; j++) bb[j] = Kt[tx + 32 * j][k];
#pragma unroll
                for (int u = 0; u < 4; u++)
#pragma unroll
                    for (int j = 0; j < 5; j++) acc[u][j] += a[u] * bb[j];
            }
            __syncthreads();
        }
        if (tid < tcnt) dsh[tid] = dloc;
        __syncthreads();
#pragma unroll
        for (int u = 0; u < 4; u++)
#pragma unroll
            for (int j = 0; j < 5; j++) {
                int col = tx + 32 * j;
                if (col < tcnt)
                    wsc[ty + 8 * u][col] = (acc[u][j] + dsh[col]) * SCORE_SCALE;
            }
    }
    __syncthreads();

    // ---- Phase B: per-row exp + L2 renorm -------------------------------
#pragma unroll
    for (int u = 0; u < 4; u++) {
        const int row = ty + 8 * u;
        const int s   = s0 + row;
        const bool valid = (s < S_LEN);
        const int lo = valid ? (max(0, s - BAND) - tlo) : 0;
        const int hi = valid ? (min(S_LEN - 1, s + BAND) - tlo) : -1;

        float m = -3.0e38f;
        for (int j = tx; j < tcnt; j += 32)
            if (j >= lo && j <= hi) m = fmaxf(m, wsc[row][j]);
#pragma unroll
        for (int o = 16; o > 0; o >>= 1) m = fmaxf(m, __shfl_xor_sync(0xffffffffu, m, o));

        float sq = 0.0f;
        for (int j = tx; j < tcnt; j += 32) {
            float e = 0.0f;
            if (j >= lo && j <= hi) {
                e = expf(wsc[row][j] - m);
                sq += e * e;
            }
            wsc[row][j] = e;
        }
#pragma unroll
        for (int o = 16; o > 0; o >>= 1) sq += __shfl_xor_sync(0xffffffffu, sq, o);

        const float inv = (valid && sq > 0.0f) ? (1.0f / sqrtf(sq)) : 0.0f;
        for (int j = tx; j < tcnt; j += 32) wsc[row][j] *= inv;
        __syncwarp();

        if (valid && outA) {
            float* arow = outA + (size_t)(b * S_LEN + s) * S_LEN + tlo;
            for (int j = lo + tx; j <= hi; j += 32) arow[j] = wsc[row][j];
        }
    }
    __syncthreads();

    // ---- Phase C: compound GEMM, two 256-col halves ---------------------
#pragma unroll 1
    for (int half = 0; half < 2; half++) {
        const int c0 = half * 256;
        float cacc[4][8];
#pragma unroll
        for (int u = 0; u < 4; u++)
#pragma unroll
            for (int j = 0; j < 8; j++) cacc[u][j] = 0.0f;

        for (int tt = 0; tt < tcnt; tt += 4) {
            const int nload = min(4, tcnt - tt);
            {
                const int row = tid >> 6;             // 0..3
                if (row < nload)
                    ((float4*)vstage)[tid] =
                        *(const float4*)(V + (size_t)(tlo + tt + row) * 512 + c0 + (tid & 63) * 4);
            }
            __syncthreads();
#pragma unroll
            for (int u2 = 0; u2 < 4; u2++) {
                if (u2 >= nload) break;
                float wt[4];
#pragma unroll
                for (int u = 0; u < 4; u++) wt[u] = wsc[ty + 8 * u][tt + u2];
#pragma unroll
                for (int j = 0; j < 8; j++) {
                    float v = vstage[u2 * 256 + tx + 32 * j];
#pragma unroll
                    for (int u = 0; u < 4; u++) cacc[u][j] += wt[u] * v;
                }
            }
            __syncthreads();
        }

        if (outC) {
#pragma unroll
            for (int u = 0; u < 4; u++) {
                const int s = s0 + ty + 8 * u;
                if (s >= S_LEN) continue;
                float* crow = outC + (size_t)(b * S_LEN + s) * DIM + c0;
#pragma unroll
                for (int j = 0; j < 8; j++) crow[tx + 32 * j] = cacc[u][j];
            }
        }
    }
}

// ---------------------------------------------------------------------------
extern "C" void kernel_launch(void* const* d_in, const int* in_sizes, int n_in,
                              void* d_out, int out_size)
{
    const float* x  = (const float*)d_in[0];
    const float* Wq = (const float*)d_in[1];
    const float* bq = (const float*)d_in[2];
    const float* Wk = (const float*)d_in[3];
    // d_in[4] = bk: cancels (per-row-s constant in exp/L2-renorm)
    const float* Wv = (const float*)d_in[5];
    const float* bv = (const float*)d_in[6];

    float* out = (float*)d_out;
    const long long NC = (long long)MROWS * DIM;
    const long long NA = (long long)MROWS * S_LEN;

    float* comp = nullptr;
    float* attn = nullptr;
    if ((long long)out_size >= NC + NA) { comp = out; attn = out + NC; }
    else if ((long long)out_size == NA) { attn = out; }
    else                                { comp = out; }

    if (attn) cudaMemsetAsync(attn, 0, (size_t)NA * sizeof(float), 0);

    conv_x<<<(PADROWS * 512 / 4 + 255) / 256, 256>>>(x);
    prep_w<<<2, 256>>>(Wk, bq);
    wqwk_gemm<<<dim3(4, 4), 256>>>(Wq, Wk);
    conv_w<<<dim3(16, 16, 2), dim3(32, 8)>>>(Wv);

    cudaFuncSetAttribute(qkv_mma, cudaFuncAttributeMaxDynamicSharedMemorySize, QKV_SMEM);
    qkv_mma<<<dim3(126, 8), 256, QKV_SMEM>>>(bv);

    dim3 g2((S_LEN + STILE - 1) / STILE, NBATCH);
    band_attn<<<g2, 256>>>(comp, attn, x);
}

// round 13
// speedup vs baseline: 1.6329x; 1.1300x over previous
#include <cuda_runtime.h>
#include <cuda_fp16.h>
#include <math.h>
#include <stdint.h>

#define S_LEN 1001
#define NBATCH 16
#define DIM 512
#define BAND 50
#define MROWS (NBATCH * S_LEN)            // 16016
#define PADROWS 16128                     // 126*128, loader-safe padding
#define SCORE_SCALE 0.044194173824159216f // 1/sqrt(512)
#define STILE 32
#define TCMAX 136
#define WSCALE 32.0f                      // W pre-scale (subnormal guard)
#define INV_WSCALE 0.03125f

// fp32 scratch: slice 0 = G = x @ (Wq Wk^T), slice 1 = V
__device__ float g_QKV[(size_t)2 * MROWS * DIM];
__device__ float g_M[512 * 512];          // Wq @ Wk^T
__device__ float g_w[512];                // Wk @ bq
// pre-split fp16 operands (W side pre-scaled by 32)
__device__ __half g_xh[(size_t)PADROWS * 512];
__device__ __half g_xl[(size_t)PADROWS * 512];
__device__ __half g_Bh[2 * 512 * 512];    // [mat][n][k], mat 0=M, 1=Wv
__device__ __half g_Bl[2 * 512 * 512];

// ---------------------------------------------------------------------------
__global__ void prep_w(const float* __restrict__ Wk, const float* __restrict__ bq)
{
    const int i = blockIdx.x * 256 + threadIdx.x;
    if (i < 512) {
        float s = 0.0f;
        const float* row = Wk + (size_t)i * 512;
#pragma unroll 8
        for (int d = 0; d < 512; d++) s += row[d] * bq[d];
        g_w[i] = s;
    }
}

// ---------------------------------------------------------------------------
// conv_x: split x into fp16 hi/lo; zero-fill padding rows.
// ---------------------------------------------------------------------------
__global__ void conv_x(const float* __restrict__ x)
{
    const size_t i = ((size_t)blockIdx.x * 256 + threadIdx.x) * 4;
    if (i >= (size_t)PADROWS * 512) return;
    float4 v = make_float4(0.f, 0.f, 0.f, 0.f);
    if (i < (size_t)MROWS * 512) v = *(const float4*)(x + i);
    float f[4] = {v.x, v.y, v.z, v.w};
    __half h[4], l[4];
#pragma unroll
    for (int j = 0; j < 4; j++) {
        h[j] = __float2half_rn(f[j]);
        l[j] = __float2half_rn(f[j] - __half2float(h[j]));
    }
    uint2 ph, pl;
    ph.x = ((uint32_t)__half_as_ushort(h[1]) << 16) | __half_as_ushort(h[0]);
    ph.y = ((uint32_t)__half_as_ushort(h[3]) << 16) | __half_as_ushort(h[2]);
    pl.x = ((uint32_t)__half_as_ushort(l[1]) << 16) | __half_as_ushort(l[0]);
    pl.y = ((uint32_t)__half_as_ushort(l[3]) << 16) | __half_as_ushort(l[2]);
    *(uint2*)&g_xh[i] = ph;
    *(uint2*)&g_xl[i] = pl;
}

// ---------------------------------------------------------------------------
// conv_w: transpose+split (32*W)[k][n] -> Bt[n][k] fp16 hi/lo. z: 0=g_M, 1=Wv.
// ---------------------------------------------------------------------------
__global__ void conv_w(const float* __restrict__ Wv)
{
    __shared__ float t[32][33];
    const int z  = blockIdx.z;
    const float* __restrict__ W = z ? Wv : g_M;
    const int k0 = blockIdx.x * 32, n0 = blockIdx.y * 32;
    const int tx = threadIdx.x, ty = threadIdx.y;

    for (int r = ty; r < 32; r += 8)
        t[r][tx] = W[(size_t)(k0 + r) * 512 + n0 + tx];
    __syncthreads();
    const size_t base = (size_t)z * 512 * 512;
    for (int r = ty; r < 32; r += 8) {
        float v = t[tx][r] * WSCALE;              // = 32*W[k0+tx][n0+r]
        __half h = __float2half_rn(v);
        g_Bh[base + (size_t)(n0 + r) * 512 + k0 + tx] = h;
        g_Bl[base + (size_t)(n0 + r) * 512 + k0 + tx] =
            __float2half_rn(v - __half2float(h));
    }
}

// ---------------------------------------------------------------------------
// wqwk_gemm: M = Wq @ Wk^T (fp32).
// ---------------------------------------------------------------------------
__global__ __launch_bounds__(256) void wqwk_gemm(const float* __restrict__ Wq,
                                                 const float* __restrict__ Wk)
{
    __shared__ __align__(16) float As[16][128];
    __shared__ __align__(16) float Bs[16][128];

    const int tid = threadIdx.x;
    const int m0  = blockIdx.x * 128;
    const int n0  = blockIdx.y * 128;
    const int tx = tid & 15, ty = tid >> 4;

    float c[8][8];
#pragma unroll
    for (int i = 0; i < 8; i++)
#pragma unroll
        for (int j = 0; j < 8; j++) c[i][j] = 0.0f;

    for (int kk = 0; kk < 512; kk += 16) {
#pragma unroll
        for (int l = 0; l < 2; l++) {
            int fid = tid + l * 256;
            int r = fid >> 2, k4 = (fid & 3) * 4;
            float4 av = *(const float4*)(Wq + (size_t)(m0 + r) * 512 + kk + k4);
            As[k4+0][r] = av.x; As[k4+1][r] = av.y; As[k4+2][r] = av.z; As[k4+3][r] = av.w;
            float4 bv = *(const float4*)(Wk + (size_t)(n0 + r) * 512 + kk + k4);
            Bs[k4+0][r] = bv.x; Bs[k4+1][r] = bv.y; Bs[k4+2][r] = bv.z; Bs[k4+3][r] = bv.w;
        }
        __syncthreads();
#pragma unroll
        for (int k = 0; k < 16; k++) {
            float4 a0 = *(float4*)&As[k][ty * 4];
            float4 a1 = *(float4*)&As[k][64 + ty * 4];
            float4 b0 = *(float4*)&Bs[k][tx * 4];
            float4 b1 = *(float4*)&Bs[k][64 + tx * 4];
            float a[8]  = {a0.x, a0.y, a0.z, a0.w, a1.x, a1.y, a1.z, a1.w};
            float bb[8] = {b0.x, b0.y, b0.z, b0.w, b1.x, b1.y, b1.z, b1.w};
#pragma unroll
            for (int i = 0; i < 8; i++)
#pragma unroll
                for (int j = 0; j < 8; j++) c[i][j] += a[i] * bb[j];
        }
        __syncthreads();
    }
#pragma unroll
    for (int i = 0; i < 8; i++) {
        int lr = (i < 4) ? (ty * 4 + i) : (64 + ty * 4 + (i - 4));
        float* orow = g_M + (size_t)(m0 + lr) * 512 + n0;
        float4 v0 = {c[i][0], c[i][1], c[i][2], c[i][3]};
        float4 v1 = {c[i][4], c[i][5], c[i][6], c[i][7]};
        *(float4*)(orow + tx * 4) = v0;
        *(float4*)(orow + 64 + tx * 4) = v1;
    }
}

// ===========================================================================
// qkv_mma: out = x @ W (+ b), mma.sync fp16, ldmatrix.x4, cp.async dbuf.
// mat==0 (G): 3-term split (hh+hl+lh). mat==1 (V): single hh pass.
// Grid (126, 8): y>>2 -> 0=G, 1=V. CTA 128x128, BK=32, stride-40 smem rows.
// ===========================================================================
#define KS 40
#define ARR_BYTES (128 * KS * 2)      // 10240
#define BUF_BYTES (4 * ARR_BYTES)     // 40960
#define QKV_SMEM  (2 * BUF_BYTES)     // 81920

__device__ __forceinline__ void mma16816(float* c, const uint32_t* a, const uint32_t* b) {
    asm volatile(
        "mma.sync.aligned.m16n8k16.row.col.f32.f16.f16.f32 "
        "{%0,%1,%2,%3}, {%4,%5,%6,%7}, {%8,%9}, {%0,%1,%2,%3};"
        : "+f"(c[0]), "+f"(c[1]), "+f"(c[2]), "+f"(c[3])
        : "r"(a[0]), "r"(a[1]), "r"(a[2]), "r"(a[3]), "r"(b[0]), "r"(b[1]));
}
__device__ __forceinline__ void ldsm4(uint32_t* r, uint32_t addr) {
    asm volatile("ldmatrix.sync.aligned.m8n8.x4.shared.b16 {%0,%1,%2,%3}, [%4];"
                 : "=r"(r[0]), "=r"(r[1]), "=r"(r[2]), "=r"(r[3]) : "r"(addr));
}
__device__ __forceinline__ void cp16(uint32_t dst, const void* src) {
    asm volatile("cp.async.cg.shared.global [%0], [%1], 16;"
                 :: "r"(dst), "l"(src) : "memory");
}

__global__ __launch_bounds__(256) void qkv_mma(const float* __restrict__ bv)
{
    extern __shared__ char dynsmem[];
    const int tid  = threadIdx.x;
    const int wid  = tid >> 5;
    const int lane = tid & 31;
    const int m0   = blockIdx.x * 128;
    const int mat  = blockIdx.y >> 2;     // 0=G, 1=V
    const int n0   = (blockIdx.y & 3) * 128;

    const size_t boff = (size_t)mat * 512 * 512;
    float* outp = g_QKV + (size_t)mat * MROWS * DIM;

    const int mw = wid >> 1;
    const int nw = wid & 1;
    const int g  = lane >> 2;
    const int tg = lane & 3;

    const uint32_t sbase = (uint32_t)__cvta_generic_to_shared(dynsmem);

    float acc[2][8][4];
#pragma unroll
    for (int f = 0; f < 2; f++)
#pragma unroll
        for (int nf = 0; nf < 8; nf++)
#pragma unroll
            for (int e = 0; e < 4; e++) acc[f][nf][e] = 0.0f;

    // ---- loader coords ----
    const int lar = tid >> 1;             // 0..127
    const int lac = (tid & 1) * 16;       // 0 or 16
    const __half* __restrict__ srcAH = g_xh + (size_t)(m0 + lar) * 512;
    const __half* __restrict__ srcAL = g_xl + (size_t)(m0 + lar) * 512;
    const __half* __restrict__ srcBH = g_Bh + boff + (size_t)(n0 + lar) * 512;
    const __half* __restrict__ srcBL = g_Bl + boff + (size_t)(n0 + lar) * 512;
    const uint32_t dstrow = (uint32_t)(lar * KS) * 2;

    // ---- ldmatrix per-thread offsets ----
    const uint32_t aoff = (uint32_t)((mw * 32 + (lane & 15)) * KS + (lane >> 4) * 8) * 2;
    const int browoff = ((lane >> 4) << 3) + (lane & 7);
    const int bcol8   = ((lane >> 3) & 1) * 8;
    const uint32_t boffm = (uint32_t)((nw * 64 + browoff) * KS + bcol8) * 2;

    // ---- prologue: prefetch chunk 0 into buffer 0 ----
    {
        const uint32_t d = sbase;
#pragma unroll
        for (int j = 0; j < 2; j++) {
            const int col = lac + 8 * j;
            const uint32_t cb = dstrow + (uint32_t)col * 2;
            cp16(d + 0 * ARR_BYTES + cb, srcAH + col);
            cp16(d + 2 * ARR_BYTES + cb, srcBH + col);
            if (mat == 0) {
                cp16(d + 1 * ARR_BYTES + cb, srcAL + col);
                cp16(d + 3 * ARR_BYTES + cb, srcBL + col);
            }
        }
        asm volatile("cp.async.commit_group;" ::: "memory");
    }

    for (int c = 0; c < 16; c++) {
        const int buf = c & 1;
        asm volatile("cp.async.wait_group 0;" ::: "memory");
        __syncthreads();

        if (c < 15) {   // prefetch chunk c+1 into the other buffer
            const int k0n = (c + 1) * 32;
            const uint32_t d = sbase + (buf ^ 1) * BUF_BYTES;
#pragma unroll
            for (int j = 0; j < 2; j++) {
                const int col = lac + 8 * j;
                const uint32_t cb = dstrow + (uint32_t)col * 2;
                cp16(d + 0 * ARR_BYTES + cb, srcAH + k0n + col);
                cp16(d + 2 * ARR_BYTES + cb, srcBH + k0n + col);
                if (mat == 0) {
                    cp16(d + 1 * ARR_BYTES + cb, srcAL + k0n + col);
                    cp16(d + 3 * ARR_BYTES + cb, srcBL + k0n + col);
                }
            }
            asm volatile("cp.async.commit_group;" ::: "memory");
        }

        // ---- compute on buffer buf ----
        const uint32_t base = sbase + buf * BUF_BYTES;
        const uint32_t aH0 = base + 0 * ARR_BYTES + aoff;
        const uint32_t aL0 = base + 1 * ARR_BYTES + aoff;
        const uint32_t bH0 = base + 2 * ARR_BYTES + boffm;
        const uint32_t bL0 = base + 3 * ARR_BYTES + boffm;

        if (mat == 0) {
#pragma unroll
            for (int s = 0; s < 2; s++) {
                const uint32_t so = (uint32_t)s * 32;
                uint32_t aH[2][4], aL[2][4];
                ldsm4(aH[0], aH0 + so);
                ldsm4(aH[1], aH0 + 16 * KS * 2 + so);
                ldsm4(aL[0], aL0 + so);
                ldsm4(aL[1], aL0 + 16 * KS * 2 + so);
#pragma unroll
                for (int p = 0; p < 4; p++) {
                    uint32_t bh[4], bl[4];
                    ldsm4(bh, bH0 + p * (16 * KS * 2) + so);
                    ldsm4(bl, bL0 + p * (16 * KS * 2) + so);
#pragma unroll
                    for (int f = 0; f < 2; f++) {
                        mma16816(acc[f][2 * p],     aH[f], bh);
                        mma16816(acc[f][2 * p],     aH[f], bl);
                        mma16816(acc[f][2 * p],     aL[f], bh);
                        mma16816(acc[f][2 * p + 1], aH[f], bh + 2);
                        mma16816(acc[f][2 * p + 1], aH[f], bl + 2);
                        mma16816(acc[f][2 * p + 1], aL[f], bh + 2);
                    }
                }
            }
        } else {
#pragma unroll
            for (int s = 0; s < 2; s++) {
                const uint32_t so = (uint32_t)s * 32;
                uint32_t aH[2][4];
                ldsm4(aH[0], aH0 + so);
                ldsm4(aH[1], aH0 + 16 * KS * 2 + so);
#pragma unroll
                for (int p = 0; p < 4; p++) {
                    uint32_t bh[4];
                    ldsm4(bh, bH0 + p * (16 * KS * 2) + so);
#pragma unroll
                    for (int f = 0; f < 2; f++) {
                        mma16816(acc[f][2 * p],     aH[f], bh);
                        mma16816(acc[f][2 * p + 1], aH[f], bh + 2);
                    }
                }
            }
        }
    }

    // ---- epilogue: descale (W was pre-scaled x32) + bias for V ----
#pragma unroll
    for (int nf = 0; nf < 8; nf++) {
        const int col = n0 + nw * 64 + nf * 8 + 2 * tg;
        float b0 = 0.f, b1 = 0.f;
        if (mat == 1) { b0 = bv[col]; b1 = bv[col + 1]; }
#pragma unroll
        for (int f = 0; f < 2; f++) {
            const int r0 = m0 + mw * 32 + f * 16 + g;
            if (r0 < MROWS) {
                float2 v = {acc[f][nf][0] * INV_WSCALE + b0,
                            acc[f][nf][1] * INV_WSCALE + b1};
                *(float2*)(outp + (size_t)r0 * 512 + col) = v;
            }
            if (r0 + 8 < MROWS) {
                float2 v = {acc[f][nf][2] * INV_WSCALE + b0,
                            acc[f][nf][3] * INV_WSCALE + b1};
                *(float2*)(outp + (size_t)(r0 + 8) * 512 + col) = v;
            }
        }
    }
}

// ---------------------------------------------------------------------------
// Band attention (unchanged from passing R11 version).
// ---------------------------------------------------------------------------
__global__ __launch_bounds__(256) void band_attn(float* __restrict__ outC,
                                                 float* __restrict__ outA,
                                                 const float* __restrict__ x)
{
    __shared__ __align__(16) float Qs[STILE][16];
    __shared__ float Kt[TCMAX][17];
    __shared__ float wsc[STILE][TCMAX];
    __shared__ float dsh[TCMAX];
    __shared__ __align__(16) float vstage[1024];   // 4 rows x 256 cols

    const int tid = threadIdx.x;
    const int tx  = tid & 31;
    const int ty  = tid >> 5;
    const int b   = blockIdx.y;
    const int s0  = blockIdx.x * STILE;

    const int tlo  = max(0, s0 - BAND);
    const int thi  = min(S_LEN - 1, s0 + STILE - 1 + BAND);
    const int tcnt = thi - tlo + 1;

    const float* G  = g_QKV + (size_t)(b * S_LEN) * DIM;
    const float* Kx = x + (size_t)(b * S_LEN) * DIM;
    const float* V  = g_QKV + ((size_t)MROWS + b * S_LEN) * DIM;

    // ---- Phase A: scores GEMM + d_t ------------------------------------
    {
        float acc[4][5];
#pragma unroll
        for (int u = 0; u < 4; u++)
#pragma unroll
            for (int j = 0; j < 5; j++) acc[u][j] = 0.0f;
        float dloc = 0.0f;

        const int qr = tid >> 3, qk = (tid & 7) * 2;
        for (int kk = 0; kk < 512; kk += 16) {
            *(float2*)&Qs[qr][qk] =
                *(const float2*)(G + (size_t)(s0 + qr) * 512 + kk + qk);
#pragma unroll
            for (int l = 0; l < 5; l++) {
                int idx = tid + l * 256;
                int row = idx >> 3, kq = (idx & 7) * 2;
                if (row < tcnt) {
                    float2 v = *(const float2*)(Kx + (size_t)(tlo + row) * 512 + kk + kq);
                    Kt[row][kq]     = v.x;
                    Kt[row][kq + 1] = v.y;
                }
            }
            __syncthreads();

            if (tid < tcnt) {
#pragma unroll
                for (int k = 0; k < 16; k++) dloc += Kt[tid][k] * g_w[kk + k];
            }
#pragma unroll
            for (int k = 0; k < 16; k++) {
                float a[4], bb[5];
#pragma unroll
                for (int u = 0; u < 4; u++) a[u] = Qs[ty + 8 * u][k];
#pragma unroll
                for (int j = 0; j < 5; j++) bb[j] = Kt[tx + 32 * j][k];
#pragma unroll
                for (int u = 0; u < 4; u++)
#pragma unroll
                    for (int j = 0; j < 5; j++) acc[u][j] += a[u] * bb[j];
            }
            __syncthreads();
        }
        if (tid < tcnt) dsh[tid] = dloc;
        __syncthreads();
#pragma unroll
        for (int u = 0; u < 4; u++)
#pragma unroll
            for (int j = 0; j < 5; j++) {
                int col = tx + 32 * j;
                if (col < tcnt)
                    wsc[ty + 8 * u][col] = (acc[u][j] + dsh[col]) * SCORE_SCALE;
            }
    }
    __syncthreads();

    // ---- Phase B: per-row exp + L2 renorm -------------------------------
#pragma unroll
    for (int u = 0; u < 4; u++) {
        const int row = ty + 8 * u;
        const int s   = s0 + row;
        const bool valid = (s < S_LEN);
        const int lo = valid ? (max(0, s - BAND) - tlo) : 0;
        const int hi = valid ? (min(S_LEN - 1, s + BAND) - tlo) : -1;

        float m = -3.0e38f;
        for (int j = tx; j < tcnt; j += 32)
            if (j >= lo && j <= hi) m = fmaxf(m, wsc[row][j]);
#pragma unroll
        for (int o = 16; o > 0; o >>= 1) m = fmaxf(m, __shfl_xor_sync(0xffffffffu, m, o));

        float sq = 0.0f;
        for (int j = tx; j < tcnt; j += 32) {
            float e = 0.0f;
            if (j >= lo && j <= hi) {
                e = expf(wsc[row][j] - m);
                sq += e * e;
            }
            wsc[row][j] = e;
        }
#pragma unroll
        for (int o = 16; o > 0; o >>= 1) sq += __shfl_xor_sync(0xffffffffu, sq, o);

        const float inv = (valid && sq > 0.0f) ? (1.0f / sqrtf(sq)) : 0.0f;
        for (int j = tx; j < tcnt; j += 32) wsc[row][j] *= inv;
        __syncwarp();

        if (valid && outA) {
            float* arow = outA + (size_t)(b * S_LEN + s) * S_LEN + tlo;
            for (int j = lo + tx; j <= hi; j += 32) arow[j] = wsc[row][j];
        }
    }
    __syncthreads();

    // ---- Phase C: compound GEMM, two 256-col halves ---------------------
#pragma unroll 1
    for (int half = 0; half < 2; half++) {
        const int c0 = half * 256;
        float cacc[4][8];
#pragma unroll
        for (int u = 0; u < 4; u++)
#pragma unroll
            for (int j = 0; j < 8; j++) cacc[u][j] = 0.0f;

        for (int tt = 0; tt < tcnt; tt += 4) {
            const int nload = min(4, tcnt - tt);
            {
                const int row = tid >> 6;             // 0..3
                if (row < nload)
                    ((float4*)vstage)[tid] =
                        *(const float4*)(V + (size_t)(tlo + tt + row) * 512 + c0 + (tid & 63) * 4);
            }
            __syncthreads();
#pragma unroll
            for (int u2 = 0; u2 < 4; u2++) {
                if (u2 >= nload) break;
                float wt[4];
#pragma unroll
                for (int u = 0; u < 4; u++) wt[u] = wsc[ty + 8 * u][tt + u2];
#pragma unroll
                for (int j = 0; j < 8; j++) {
                    float v = vstage[u2 * 256 + tx + 32 * j];
#pragma unroll
                    for (int u = 0; u < 4; u++) cacc[u][j] += wt[u] * v;
                }
            }
            __syncthreads();
        }

        if (outC) {
#pragma unroll
            for (int u = 0; u < 4; u++) {
                const int s = s0 + ty + 8 * u;
                if (s >= S_LEN) continue;
                float* crow = outC + (size_t)(b * S_LEN + s) * DIM + c0;
#pragma unroll
                for (int j = 0; j < 8; j++) crow[tx + 32 * j] = cacc[u][j];
            }
        }
    }
}

// ---------------------------------------------------------------------------
extern "C" void kernel_launch(void* const* d_in, const int* in_sizes, int n_in,
                              void* d_out, int out_size)
{
    const float* x  = (const float*)d_in[0];
    const float* Wq = (const float*)d_in[1];
    const float* bq = (const float*)d_in[2];
    const float* Wk = (const float*)d_in[3];
    // d_in[4] = bk: cancels (per-row-s constant in exp/L2-renorm)
    const float* Wv = (const float*)d_in[5];
    const float* bv = (const float*)d_in[6];

    float* out = (float*)d_out;
    const long long NC = (long long)MROWS * DIM;
    const long long NA = (long long)MROWS * S_LEN;

    float* comp = nullptr;
    float* attn = nullptr;
    if ((long long)out_size >= NC + NA) { comp = out; attn = out + NC; }
    else if ((long long)out_size == NA) { attn = out; }
    else                                { comp = out; }

    if (attn) cudaMemsetAsync(attn, 0, (size_t)NA * sizeof(float), 0);

    conv_x<<<(PADROWS * 512 / 4 + 255) / 256, 256>>>(x);
    prep_w<<<2, 256>>>(Wk, bq);
    wqwk_gemm<<<dim3(4, 4), 256>>>(Wq, Wk);
    conv_w<<<dim3(16, 16, 2), dim3(32, 8)>>>(Wv);

    cudaFuncSetAttribute(qkv_mma, cudaFuncAttributeMaxDynamicSharedMemorySize, QKV_SMEM);
    qkv_mma<<<dim3(126, 8), 256, QKV_SMEM>>>(bv);

    dim3 g2((S_LEN + STILE - 1) / STILE, NBATCH);
    band_attn<<<g2, 256>>>(comp, attn, x);
}

// round 16
// speedup vs baseline: 1.8971x; 1.1618x over previous
#include <cuda_runtime.h>
#include <cuda_fp16.h>
#include <math.h>
#include <stdint.h>

#define S_LEN 1001
#define NBATCH 16
#define DIM 512
#define BAND 50
#define MROWS (NBATCH * S_LEN)            // 16016
#define PADROWS 16128                     // 126*128, loader-safe padding
#define SCORE_SCALE 0.044194173824159216f // 1/sqrt(512)
#define STILE 32
#define NPAD 160                          // padded band cols (132 actual)
#define WSCALE 32.0f                      // W pre-scale (subnormal guard)
#define INV_WSCALE 0.03125f

// V stays fp32 (phase C SIMT). G lives only as fp16 hi/lo.
__device__ float g_V[(size_t)MROWS * DIM];
__device__ float g_M[512 * 512];          // Wq @ Wk^T
__device__ float g_w[512];                // Wk @ bq
__device__ float g_d[PADROWS];            // x . g_w per row (pad rows = 0)
// pre-split fp16 operands (W side pre-scaled by 32)
__device__ __half g_xh[(size_t)PADROWS * 512];
__device__ __half g_xl[(size_t)PADROWS * 512];
__device__ __half g_Gh[(size_t)PADROWS * 512];   // pad rows stay zero-init
__device__ __half g_Gl[(size_t)PADROWS * 512];
__device__ __half g_Bh[2 * 512 * 512];    // [mat][n][k], mat 0=M, 1=Wv
__device__ __half g_Bl[2 * 512 * 512];

// ---------------------------------------------------------------------------
__global__ void prep_w(const float* __restrict__ Wk, const float* __restrict__ bq)
{
    const int i = blockIdx.x * 256 + threadIdx.x;
    if (i < 512) {
        float s = 0.0f;
        const float* row = Wk + (size_t)i * 512;
#pragma unroll 8
        for (int d = 0; d < 512; d++) s += row[d] * bq[d];
        g_w[i] = s;
    }
}

// ---------------------------------------------------------------------------
// prep_d: g_d[r] = x[r,:] . g_w  (warp per row); pad rows -> 0.
// ---------------------------------------------------------------------------
__global__ void prep_d(const float* __restrict__ x)
{
    const int row  = blockIdx.x * 8 + (threadIdx.x >> 5);
    const int lane = threadIdx.x & 31;
    if (row >= PADROWS) return;
    float d = 0.0f;
    if (row < MROWS) {
        const float* xr = x + (size_t)row * 512;
#pragma unroll
        for (int j = 0; j < 16; j++) d += xr[lane + 32 * j] * g_w[lane + 32 * j];
#pragma unroll
        for (int o = 16; o > 0; o >>= 1) d += __shfl_xor_sync(0xffffffffu, d, o);
    }
    if (lane == 0) g_d[row] = d;
}

// ---------------------------------------------------------------------------
// conv_x: split x into fp16 hi/lo; zero-fill padding rows.
// ---------------------------------------------------------------------------
__global__ void conv_x(const float* __restrict__ x)
{
    const size_t i = ((size_t)blockIdx.x * 256 + threadIdx.x) * 4;
    if (i >= (size_t)PADROWS * 512) return;
    float4 v = make_float4(0.f, 0.f, 0.f, 0.f);
    if (i < (size_t)MROWS * 512) v = *(const float4*)(x + i);
    float f[4] = {v.x, v.y, v.z, v.w};
    __half h[4], l[4];
#pragma unroll
    for (int j = 0; j < 4; j++) {
        h[j] = __float2half_rn(f[j]);
        l[j] = __float2half_rn(f[j] - __half2float(h[j]));
    }
    uint2 ph, pl;
    ph.x = ((uint32_t)__half_as_ushort(h[1]) << 16) | __half_as_ushort(h[0]);
    ph.y = ((uint32_t)__half_as_ushort(h[3]) << 16) | __half_as_ushort(h[2]);
    pl.x = ((uint32_t)__half_as_ushort(l[1]) << 16) | __half_as_ushort(l[0]);
    pl.y = ((uint32_t)__half_as_ushort(l[3]) << 16) | __half_as_ushort(l[2]);
    *(uint2*)&g_xh[i] = ph;
    *(uint2*)&g_xl[i] = pl;
}

// ---------------------------------------------------------------------------
// conv_w: transpose+split (32*W)[k][n] -> Bt[n][k] fp16 hi/lo. z: 0=g_M, 1=Wv.
// ---------------------------------------------------------------------------
__global__ void conv_w(const float* __restrict__ Wv)
{
    __shared__ float t[32][33];
    const int z  = blockIdx.z;
    const float* __restrict__ W = z ? Wv : g_M;
    const int k0 = blockIdx.x * 32, n0 = blockIdx.y * 32;
    const int tx = threadIdx.x, ty = threadIdx.y;

    for (int r = ty; r < 32; r += 8)
        t[r][tx] = W[(size_t)(k0 + r) * 512 + n0 + tx];
    __syncthreads();
    const size_t base = (size_t)z * 512 * 512;
    for (int r = ty; r < 32; r += 8) {
        float v = t[tx][r] * WSCALE;              // = 32*W[k0+tx][n0+r]
        __half h = __float2half_rn(v);
        g_Bh[base + (size_t)(n0 + r) * 512 + k0 + tx] = h;
        g_Bl[base + (size_t)(n0 + r) * 512 + k0 + tx] =
            __float2half_rn(v - __half2float(h));
    }
}

// ---------------------------------------------------------------------------
// wqwk_gemm: M = Wq @ Wk^T (fp32).
// ---------------------------------------------------------------------------
__global__ __launch_bounds__(256) void wqwk_gemm(const float* __restrict__ Wq,
                                                 const float* __restrict__ Wk)
{
    __shared__ __align__(16) float As[16][128];
    __shared__ __align__(16) float Bs[16][128];

    const int tid = threadIdx.x;
    const int m0  = blockIdx.x * 128;
    const int n0  = blockIdx.y * 128;
    const int tx = tid & 15, ty = tid >> 4;

    float c[8][8];
#pragma unroll
    for (int i = 0; i < 8; i++)
#pragma unroll
        for (int j = 0; j < 8; j++) c[i][j] = 0.0f;

    for (int kk = 0; kk < 512; kk += 16) {
#pragma unroll
        for (int l = 0; l < 2; l++) {
            int fid = tid + l * 256;
            int r = fid >> 2, k4 = (fid & 3) * 4;
            float4 av = *(const float4*)(Wq + (size_t)(m0 + r) * 512 + kk + k4);
            As[k4+0][r] = av.x; As[k4+1][r] = av.y; As[k4+2][r] = av.z; As[k4+3][r] = av.w;
            float4 bv = *(const float4*)(Wk + (size_t)(n0 + r) * 512 + kk + k4);
            Bs[k4+0][r] = bv.x; Bs[k4+1][r] = bv.y; Bs[k4+2][r] = bv.z; Bs[k4+3][r] = bv.w;
        }
        __syncthreads();
#pragma unroll
        for (int k = 0; k < 16; k++) {
            float4 a0 = *(float4*)&As[k][ty * 4];
            float4 a1 = *(float4*)&As[k][64 + ty * 4];
            float4 b0 = *(float4*)&Bs[k][tx * 4];
            float4 b1 = *(float4*)&Bs[k][64 + tx * 4];
            float a[8]  = {a0.x, a0.y, a0.z, a0.w, a1.x, a1.y, a1.z, a1.w};
            float bb[8] = {b0.x, b0.y, b0.z, b0.w, b1.x, b1.y, b1.z, b1.w};
#pragma unroll
            for (int i = 0; i < 8; i++)
#pragma unroll
                for (int j = 0; j < 8; j++) c[i][j] += a[i] * bb[j];
        }
        __syncthreads();
    }
#pragma unroll
    for (int i = 0; i < 8; i++) {
        int lr = (i < 4) ? (ty * 4 + i) : (64 + ty * 4 + (i - 4));
        float* orow = g_M + (size_t)(m0 + lr) * 512 + n0;
        float4 v0 = {c[i][0], c[i][1], c[i][2], c[i][3]};
        float4 v1 = {c[i][4], c[i][5], c[i][6], c[i][7]};
        *(float4*)(orow + tx * 4) = v0;
        *(float4*)(orow + 64 + tx * 4) = v1;
    }
}

// ===========================================================================
// Shared MMA helpers
// ===========================================================================
#define KS 40
#define ARR_BYTES (128 * KS * 2)      // 10240
#define BUF_BYTES (4 * ARR_BYTES)     // 40960
#define QKV_SMEM  (2 * BUF_BYTES)     // 81920

__device__ __forceinline__ void mma16816(float* c, const uint32_t* a, const uint32_t* b) {
    asm volatile(
        "mma.sync.aligned.m16n8k16.row.col.f32.f16.f16.f32 "
        "{%0,%1,%2,%3}, {%4,%5,%6,%7}, {%8,%9}, {%0,%1,%2,%3};"
        : "+f"(c[0]), "+f"(c[1]), "+f"(c[2]), "+f"(c[3])
        : "r"(a[0]), "r"(a[1]), "r"(a[2]), "r"(a[3]), "r"(b[0]), "r"(b[1]));
}
__device__ __forceinline__ void ldsm4(uint32_t* r, uint32_t addr) {
    asm volatile("ldmatrix.sync.aligned.m8n8.x4.shared.b16 {%0,%1,%2,%3}, [%4];"
                 : "=r"(r[0]), "=r"(r[1]), "=r"(r[2]), "=r"(r[3]) : "r"(addr));
}
__device__ __forceinline__ void ldsm2(uint32_t* r, uint32_t addr) {
    asm volatile("ldmatrix.sync.aligned.m8n8.x2.shared.b16 {%0,%1}, [%2];"
                 : "=r"(r[0]), "=r"(r[1]) : "r"(addr));
}
__device__ __forceinline__ void cp16(uint32_t dst, const void* src) {
    asm volatile("cp.async.cg.shared.global [%0], [%1], 16;"
                 :: "r"(dst), "l"(src) : "memory");
}

// ===========================================================================
// qkv_mma: mma.sync fp16, ldmatrix.x4, cp.async dbuf.
// mat==0 (G): 3-term split, epilogue writes fp16 hi/lo G.
// mat==1 (V): single hh pass, epilogue writes fp32 V + bias.
// ===========================================================================
__global__ __launch_bounds__(256) void qkv_mma(const float* __restrict__ bv)
{
    extern __shared__ char dynsmem[];
    const int tid  = threadIdx.x;
    const int wid  = tid >> 5;
    const int lane = tid & 31;
    const int m0   = blockIdx.x * 128;
    const int mat  = blockIdx.y >> 2;     // 0=G, 1=V
    const int n0   = (blockIdx.y & 3) * 128;

    const size_t boff = (size_t)mat * 512 * 512;

    const int mw = wid >> 1;
    const int nw = wid & 1;
    const int g  = lane >> 2;
    const int tg = lane & 3;

    const uint32_t sbase = (uint32_t)__cvta_generic_to_shared(dynsmem);

    float acc[2][8][4];
#pragma unroll
    for (int f = 0; f < 2; f++)
#pragma unroll
        for (int nf = 0; nf < 8; nf++)
#pragma unroll
            for (int e = 0; e < 4; e++) acc[f][nf][e] = 0.0f;

    const int lar = tid >> 1;
    const int lac = (tid & 1) * 16;
    const __half* __restrict__ srcAH = g_xh + (size_t)(m0 + lar) * 512;
    const __half* __restrict__ srcAL = g_xl + (size_t)(m0 + lar) * 512;
    const __half* __restrict__ srcBH = g_Bh + boff + (size_t)(n0 + lar) * 512;
    const __half* __restrict__ srcBL = g_Bl + boff + (size_t)(n0 + lar) * 512;
    const uint32_t dstrow = (uint32_t)(lar * KS) * 2;

    const uint32_t aoff = (uint32_t)((mw * 32 + (lane & 15)) * KS + (lane >> 4) * 8) * 2;
    const int browoff = ((lane >> 4) << 3) + (lane & 7);
    const int bcol8   = ((lane >> 3) & 1) * 8;
    const uint32_t boffm = (uint32_t)((nw * 64 + browoff) * KS + bcol8) * 2;

    {
        const uint32_t d = sbase;
#pragma unroll
        for (int j = 0; j < 2; j++) {
            const int col = lac + 8 * j;
            const uint32_t cb = dstrow + (uint32_t)col * 2;
            cp16(d + 0 * ARR_BYTES + cb, srcAH + col);
            cp16(d + 2 * ARR_BYTES + cb, srcBH + col);
            if (mat == 0) {
                cp16(d + 1 * ARR_BYTES + cb, srcAL + col);
                cp16(d + 3 * ARR_BYTES + cb, srcBL + col);
            }
        }
        asm volatile("cp.async.commit_group;" ::: "memory");
    }

    for (int c = 0; c < 16; c++) {
        const int buf = c & 1;
        asm volatile("cp.async.wait_group 0;" ::: "memory");
        __syncthreads();

        if (c < 15) {
            const int k0n = (c + 1) * 32;
            const uint32_t d = sbase + (buf ^ 1) * BUF_BYTES;
#pragma unroll
            for (int j = 0; j < 2; j++) {
                const int col = lac + 8 * j;
                const uint32_t cb = dstrow + (uint32_t)col * 2;
                cp16(d + 0 * ARR_BYTES + cb, srcAH + k0n + col);
                cp16(d + 2 * ARR_BYTES + cb, srcBH + k0n + col);
                if (mat == 0) {
                    cp16(d + 1 * ARR_BYTES + cb, srcAL + k0n + col);
                    cp16(d + 3 * ARR_BYTES + cb, srcBL + k0n + col);
                }
            }
            asm volatile("cp.async.commit_group;" ::: "memory");
        }

        const uint32_t base = sbase + buf * BUF_BYTES;
        const uint32_t aH0 = base + 0 * ARR_BYTES + aoff;
        const uint32_t aL0 = base + 1 * ARR_BYTES + aoff;
        const uint32_t bH0 = base + 2 * ARR_BYTES + boffm;
        const uint32_t bL0 = base + 3 * ARR_BYTES + boffm;

        if (mat == 0) {
#pragma unroll
            for (int s = 0; s < 2; s++) {
                const uint32_t so = (uint32_t)s * 32;
                uint32_t aH[2][4], aL[2][4];
                ldsm4(aH[0], aH0 + so);
                ldsm4(aH[1], aH0 + 16 * KS * 2 + so);
                ldsm4(aL[0], aL0 + so);
                ldsm4(aL[1], aL0 + 16 * KS * 2 + so);
#pragma unroll
                for (int p = 0; p < 4; p++) {
                    uint32_t bh[4], bl[4];
                    ldsm4(bh, bH0 + p * (16 * KS * 2) + so);
                    ldsm4(bl, bL0 + p * (16 * KS * 2) + so);
#pragma unroll
                    for (int f = 0; f < 2; f++) {
                        mma16816(acc[f][2 * p],     aH[f], bh);
                        mma16816(acc[f][2 * p],     aH[f], bl);
                        mma16816(acc[f][2 * p],     aL[f], bh);
                        mma16816(acc[f][2 * p + 1], aH[f], bh + 2);
                        mma16816(acc[f][2 * p + 1], aH[f], bl + 2);
                        mma16816(acc[f][2 * p + 1], aL[f], bh + 2);
                    }
                }
            }
        } else {
#pragma unroll
            for (int s = 0; s < 2; s++) {
                const uint32_t so = (uint32_t)s * 32;
                uint32_t aH[2][4];
                ldsm4(aH[0], aH0 + so);
                ldsm4(aH[1], aH0 + 16 * KS * 2 + so);
#pragma unroll
                for (int p = 0; p < 4; p++) {
                    uint32_t bh[4];
                    ldsm4(bh, bH0 + p * (16 * KS * 2) + so);
#pragma unroll
                    for (int f = 0; f < 2; f++) {
                        mma16816(acc[f][2 * p],     aH[f], bh);
                        mma16816(acc[f][2 * p + 1], aH[f], bh + 2);
                    }
                }
            }
        }
    }

    // ---- epilogue ----
    if (mat == 1) {
#pragma unroll
        for (int nf = 0; nf < 8; nf++) {
            const int col = n0 + nw * 64 + nf * 8 + 2 * tg;
            const float b0 = bv[col], b1 = bv[col + 1];
#pragma unroll
            for (int f = 0; f < 2; f++) {
                const int r0 = m0 + mw * 32 + f * 16 + g;
                if (r0 < MROWS) {
                    float2 v = {acc[f][nf][0] * INV_WSCALE + b0,
                                acc[f][nf][1] * INV_WSCALE + b1};
                    *(float2*)(g_V + (size_t)r0 * 512 + col) = v;
                }
                if (r0 + 8 < MROWS) {
                    float2 v = {acc[f][nf][2] * INV_WSCALE + b0,
                                acc[f][nf][3] * INV_WSCALE + b1};
                    *(float2*)(g_V + (size_t)(r0 + 8) * 512 + col) = v;
                }
            }
        }
    } else {
#pragma unroll
        for (int nf = 0; nf < 8; nf++) {
            const int col = n0 + nw * 64 + nf * 8 + 2 * tg;
#pragma unroll
            for (int f = 0; f < 2; f++) {
#pragma unroll
                for (int half = 0; half < 2; half++) {
                    const int r = m0 + mw * 32 + f * 16 + g + 8 * half;
                    if (r >= MROWS) continue;
                    float v0 = acc[f][nf][2 * half]     * INV_WSCALE;
                    float v1 = acc[f][nf][2 * half + 1] * INV_WSCALE;
                    __half h0 = __float2half_rn(v0), h1 = __float2half_rn(v1);
                    __half l0 = __float2half_rn(v0 - __half2float(h0));
                    __half l1 = __float2half_rn(v1 - __half2float(h1));
                    *(uint32_t*)&g_Gh[(size_t)r * 512 + col] =
                        ((uint32_t)__half_as_ushort(h1) << 16) | __half_as_ushort(h0);
                    *(uint32_t*)&g_Gl[(size_t)r * 512 + col] =
                        ((uint32_t)__half_as_ushort(l1) << 16) | __half_as_ushort(l0);
                }
            }
        }
    }
}

// ===========================================================================
// band_attn: phase A = tensor-core scores GEMM (32 x 160 x 512, 3-pass fp16
// split); phase B = exp + L2 renorm (fp32); phase C = fp32 SIMT compound.
// Dynamic smem: Ah(2560) Al(2560) Bh(12800) Bl(12800) = 30720 B.
// Static (25.2 KB) + dynamic (30 KB) > 48 KB -> MaxDynamicSharedMemorySize
// attribute is set in kernel_launch (this was R14's failure).
// ===========================================================================
#define BA_OAH 0
#define BA_OAL 2560
#define BA_OBH 5120
#define BA_OBL 17920
#define BA_SMEM 30720

__global__ __launch_bounds__(256) void band_attn(float* __restrict__ outC,
                                                 float* __restrict__ outA)
{
    extern __shared__ char asmem[];
    __shared__ float wsc[STILE][NPAD];
    __shared__ float dsh[NPAD];
    __shared__ __align__(16) float vstage[1024];   // 4 rows x 256 cols

    const int tid  = threadIdx.x;
    const int lane = tid & 31;
    const int wid  = tid >> 5;
    const int tx   = lane;
    const int ty   = wid;
    const int b    = blockIdx.y;
    const int s0   = blockIdx.x * STILE;

    const int tlo  = max(0, s0 - BAND);
    const int thi  = min(S_LEN - 1, s0 + STILE - 1 + BAND);
    const int tcnt = thi - tlo + 1;                // <= 132

    const float* V = g_V + (size_t)(b * S_LEN) * DIM;

    if (tid < NPAD) dsh[tid] = g_d[(size_t)b * S_LEN + tlo + tid];

    // ---- Phase A: scores MMA -------------------------------------------
    {
        const uint32_t sb = (uint32_t)__cvta_generic_to_shared(asmem);
        const int mw  = wid & 1;        // m16 tile
        const int nwg = wid >> 1;       // 40-col group
        const int g   = lane >> 2;
        const int tg  = lane & 3;

        const uint32_t aoff = (uint32_t)((mw * 16 + (lane & 15)) * KS + (lane >> 4) * 8) * 2;
        const int browoff = ((lane >> 4) << 3) + (lane & 7);
        const int bcol8   = ((lane >> 3) & 1) * 8;

        float acc[5][4];
#pragma unroll
        for (int f = 0; f < 5; f++)
#pragma unroll
            for (int e = 0; e < 4; e++) acc[f][e] = 0.0f;

        const size_t arow = (size_t)(b * S_LEN + s0);
        const size_t brow = (size_t)(b * S_LEN + tlo);

        for (int c = 0; c < 16; c++) {
            const int k0 = c * 32;
            __syncthreads();
#pragma unroll
            for (int i = 0; i < 6; i++) {
                const int idx = tid + i * 256;
                if (idx < 256) {
                    const int r = (idx & 127) >> 2, c16 = idx & 3;
                    const __half* src = ((idx < 128) ? g_Gh : g_Gl)
                                        + (arow + r) * 512 + k0 + c16 * 8;
                    const uint32_t dst = sb + ((idx < 128) ? BA_OAH : BA_OAL)
                                        + (uint32_t)(r * KS + c16 * 8) * 2;
                    cp16(dst, src);
                } else {
                    const int j = idx - 256;
                    const int jj = (j < 640) ? j : j - 640;
                    const int r = jj >> 2, c16 = jj & 3;
                    const __half* src = ((j < 640) ? g_xh : g_xl)
                                        + (brow + r) * 512 + k0 + c16 * 8;
                    const uint32_t dst = sb + ((j < 640) ? BA_OBH : BA_OBL)
                                        + (uint32_t)(r * KS + c16 * 8) * 2;
                    cp16(dst, src);
                }
            }
            asm volatile("cp.async.commit_group;" ::: "memory");
            asm volatile("cp.async.wait_group 0;" ::: "memory");
            __syncthreads();

#pragma unroll
            for (int ks = 0; ks < 2; ks++) {
                const uint32_t so = (uint32_t)ks * 32;
                uint32_t aH[4], aL[4];
                ldsm4(aH, sb + BA_OAH + aoff + so);
                ldsm4(aL, sb + BA_OAL + aoff + so);
                uint32_t bh[10], bl[10];
                const uint32_t b16a = (uint32_t)((nwg * 40 + browoff) * KS + bcol8) * 2 + so;
                const uint32_t b16b = (uint32_t)((nwg * 40 + 16 + browoff) * KS + bcol8) * 2 + so;
                const uint32_t b8   = (uint32_t)((nwg * 40 + 32 + (lane & 7)) * KS + bcol8) * 2 + so;
                ldsm4(bh + 0, sb + BA_OBH + b16a);
                ldsm4(bh + 4, sb + BA_OBH + b16b);
                ldsm2(bh + 8, sb + BA_OBH + b8);
                ldsm4(bl + 0, sb + BA_OBL + b16a);
                ldsm4(bl + 4, sb + BA_OBL + b16b);
                ldsm2(bl + 8, sb + BA_OBL + b8);
#pragma unroll
                for (int f = 0; f < 5; f++) {
                    mma16816(acc[f], aH, bh + 2 * f);
                    mma16816(acc[f], aH, bl + 2 * f);
                    mma16816(acc[f], aL, bh + 2 * f);
                }
            }
        }
        __syncthreads();   // dsh ready (written at kernel start)
#pragma unroll
        for (int f = 0; f < 5; f++) {
            const int col = nwg * 40 + f * 8 + 2 * tg;
            const int r0 = mw * 16 + g;
            wsc[r0][col]     = (acc[f][0] + dsh[col])     * SCORE_SCALE;
            wsc[r0][col + 1] = (acc[f][1] + dsh[col + 1]) * SCORE_SCALE;
            wsc[r0 + 8][col]     = (acc[f][2] + dsh[col])     * SCORE_SCALE;
            wsc[r0 + 8][col + 1] = (acc[f][3] + dsh[col + 1]) * SCORE_SCALE;
        }
    }
    __syncthreads();

    // ---- Phase B: per-row exp + L2 renorm -------------------------------
#pragma unroll
    for (int u = 0; u < 4; u++) {
        const int row = ty + 8 * u;
        const int s   = s0 + row;
        const bool valid = (s < S_LEN);
        const int lo = valid ? (max(0, s - BAND) - tlo) : 0;
        const int hi = valid ? (min(S_LEN - 1, s + BAND) - tlo) : -1;

        float m = -3.0e38f;
        for (int j = tx; j < tcnt; j += 32)
            if (j >= lo && j <= hi) m = fmaxf(m, wsc[row][j]);
#pragma unroll
        for (int o = 16; o > 0; o >>= 1) m = fmaxf(m, __shfl_xor_sync(0xffffffffu, m, o));

        float sq = 0.0f;
        for (int j = tx; j < tcnt; j += 32) {
            float e = 0.0f;
            if (j >= lo && j <= hi) {
                e = expf(wsc[row][j] - m);
                sq += e * e;
            }
            wsc[row][j] = e;
        }
#pragma unroll
        for (int o = 16; o > 0; o >>= 1) sq += __shfl_xor_sync(0xffffffffu, sq, o);

        const float inv = (valid && sq > 0.0f) ? (1.0f / sqrtf(sq)) : 0.0f;
        for (int j = tx; j < tcnt; j += 32) wsc[row][j] *= inv;
        __syncwarp();

        if (valid && outA) {
            float* arow = outA + (size_t)(b * S_LEN + s) * S_LEN + tlo;
            for (int j = lo + tx; j <= hi; j += 32) arow[j] = wsc[row][j];
        }
    }
    __syncthreads();

    // ---- Phase C: compound GEMM, two 256-col halves ---------------------
#pragma unroll 1
    for (int half = 0; half < 2; half++) {
        const int c0 = half * 256;
        float cacc[4][8];
#pragma unroll
        for (int u = 0; u < 4; u++)
#pragma unroll
            for (int j = 0; j < 8; j++) cacc[u][j] = 0.0f;

        for (int tt = 0; tt < tcnt; tt += 4) {
            const int nload = min(4, tcnt - tt);
            {
                const int row = tid >> 6;             // 0..3
                if (row < nload)
                    ((float4*)vstage)[tid] =
                        *(const float4*)(V + (size_t)(tlo + tt + row) * 512 + c0 + (tid & 63) * 4);
            }
            __syncthreads();
#pragma unroll
            for (int u2 = 0; u2 < 4; u2++) {
                if (u2 >= nload) break;
                float wt[4];
#pragma unroll
                for (int u = 0; u < 4; u++) wt[u] = wsc[ty + 8 * u][tt + u2];
#pragma unroll
                for (int j = 0; j < 8; j++) {
                    float v = vstage[u2 * 256 + tx + 32 * j];
#pragma unroll
                    for (int u = 0; u < 4; u++) cacc[u][j] += wt[u] * v;
                }
            }
            __syncthreads();
        }

        if (outC) {
#pragma unroll
            for (int u = 0; u < 4; u++) {
                const int s = s0 + ty + 8 * u;
                if (s >= S_LEN) continue;
                float* crow = outC + (size_t)(b * S_LEN + s) * DIM + c0;
#pragma unroll
                for (int j = 0; j < 8; j++) crow[tx + 32 * j] = cacc[u][j];
            }
        }
    }
}

// ---------------------------------------------------------------------------
extern "C" void kernel_launch(void* const* d_in, const int* in_sizes, int n_in,
                              void* d_out, int out_size)
{
    const float* x  = (const float*)d_in[0];
    const float* Wq = (const float*)d_in[1];
    const float* bq = (const float*)d_in[2];
    const float* Wk = (const float*)d_in[3];
    // d_in[4] = bk: cancels (per-row-s constant in exp/L2-renorm)
    const float* Wv = (const float*)d_in[5];
    const float* bv = (const float*)d_in[6];

    float* out = (float*)d_out;
    const long long NC = (long long)MROWS * DIM;
    const long long NA = (long long)MROWS * S_LEN;

    float* comp = nullptr;
    float* attn = nullptr;
    if ((long long)out_size >= NC + NA) { comp = out; attn = out + NC; }
    else if ((long long)out_size == NA) { attn = out; }
    else                                { comp = out; }

    if (attn) cudaMemsetAsync(attn, 0, (size_t)NA * sizeof(float), 0);

    conv_x<<<(PADROWS * 512 / 4 + 255) / 256, 256>>>(x);
    prep_w<<<2, 256>>>(Wk, bq);
    prep_d<<<PADROWS / 8, 256>>>(x);
    wqwk_gemm<<<dim3(4, 4), 256>>>(Wq, Wk);
    conv_w<<<dim3(16, 16, 2), dim3(32, 8)>>>(Wv);

    cudaFuncSetAttribute(qkv_mma, cudaFuncAttributeMaxDynamicSharedMemorySize, QKV_SMEM);
    qkv_mma<<<dim3(126, 8), 256, QKV_SMEM>>>(bv);

    cudaFuncSetAttribute(band_attn, cudaFuncAttributeMaxDynamicSharedMemorySize, BA_SMEM);
    dim3 g2((S_LEN + STILE - 1) / STILE, NBATCH);
    band_attn<<<g2, 256, BA_SMEM>>>(comp, attn);
}